// round 11
// baseline (speedup 1.0000x reference)
#include <cuda_runtime.h>
#include <math.h>
#include <stdint.h>

#define BB_ 4
#define SS_ 2048
#define DD_ 1024
#define HH_ 16
#define DH_ 64

// ---------------- scratch (device globals: allocation-free) ----------------
__device__ float g_q[(size_t)BB_ * HH_ * SS_ * DH_];   // 33.5 MB
__device__ float g_k[(size_t)BB_ * HH_ * SS_ * DH_];
__device__ float g_v[(size_t)BB_ * HH_ * SS_ * DH_];
__device__ float g_att[(size_t)BB_ * SS_ * DD_];       // merged-head attention output
__device__ float g_wt[(size_t)3072 * 1024 + 1024 * 1024];  // W_in^T then W_out^T ([N,K])

// =============================== PTX helpers ===============================
__device__ __forceinline__ uint32_t smem_u32(const void* p) {
    uint32_t a;
    asm("{ .reg .u64 t; cvta.to.shared.u64 t, %1; cvt.u32.u64 %0, t; }"
        : "=r"(a) : "l"(p));
    return a;
}

__device__ __forceinline__ uint32_t f2tf(float x) {
    uint32_t r;
    asm("cvt.rna.tf32.f32 %0, %1;" : "=r"(r) : "f"(x));
    return r;
}

// ============================================================================
// W transpose: Wt[n*1024 + k] = W[k*N + n]   (K is always 1024 here)
// ============================================================================
__global__ void transpose_kernel(const float* __restrict__ W, int N, int out_off)
{
    __shared__ float tile[32][33];
    int n0 = blockIdx.x * 32, k0 = blockIdx.y * 32;
    int tx = threadIdx.x, ty = threadIdx.y;   // 32 x 8
#pragma unroll
    for (int i = 0; i < 32; i += 8)
        tile[ty + i][tx] = W[(size_t)(k0 + ty + i) * N + n0 + tx];
    __syncthreads();
    float* Wt = g_wt + out_off;
#pragma unroll
    for (int i = 0; i < 32; i += 8)
        Wt[(size_t)(n0 + ty + i) * 1024 + k0 + tx] = tile[tx][ty + i];
}

// ============================================================================
// TF32 mma.sync GEMM (unchanged from R10): C[M,N] = A[M,1024] @ W[1024,N] + b
// ============================================================================
#define ASTR 36
#define TILEF (128 * ASTR)
#define GSTAGES 3
#define GSMEM_BYTES (GSTAGES * 2 * TILEF * 4)   // 110,592

__device__ __forceinline__ void ld_tile(const float* __restrict__ src, int row0,
                                        int k0, float* dst, int t)
{
#pragma unroll
    for (int i = 0; i < 4; i++) {
        int idx = t + i * 256;
        int r = idx >> 3, c = idx & 7;
        const float* g = src + (size_t)(row0 + r) * 1024 + k0 + c * 4;
        uint32_t d = smem_u32(dst + r * ASTR + c * 4);
        asm volatile("cp.async.cg.shared.global [%0], [%1], 16;\n"
                     :: "r"(d), "l"(g));
    }
}

__global__ __launch_bounds__(256)
void mma_gemm(const float* __restrict__ A_, int wt_off,
              const float* __restrict__ bias, float* __restrict__ Cout,
              int Ntot, int mode)
{
    extern __shared__ __align__(16) float sm[];
    const float* A  = (mode == 1) ? g_att : A_;
    const float* Bt = g_wt + wt_off;
    float* As = sm;
    float* Bs = sm + GSTAGES * TILEF;

    const int t = threadIdx.x, wid = t >> 5, lane = t & 31;
    const int n0 = blockIdx.x * 128, m0 = blockIdx.y * 128;
    const int wm0 = (wid >> 2) * 64, wn0 = (wid & 3) * 32;
    const int ly = lane >> 2, lx = lane & 3;

    float c[4][4][4];
#pragma unroll
    for (int mf = 0; mf < 4; mf++)
#pragma unroll
        for (int nf = 0; nf < 4; nf++)
#pragma unroll
            for (int i = 0; i < 4; i++) c[mf][nf][i] = 0.f;

#pragma unroll
    for (int j = 0; j < 2; j++) {
        ld_tile(A,  m0, j * 32, As + j * TILEF, t);
        ld_tile(Bt, n0, j * 32, Bs + j * TILEF, t);
        asm volatile("cp.async.commit_group;\n" ::: "memory");
    }

    for (int kt = 0; kt < 32; kt++) {
        asm volatile("cp.async.wait_group 1;\n" ::: "memory");
        __syncthreads();

        int j = kt + 2;
        if (j < 32) {
            int s = j - (j / 3) * 3;
            ld_tile(A,  m0, j * 32, As + s * TILEF, t);
            ld_tile(Bt, n0, j * 32, Bs + s * TILEF, t);
        }
        asm volatile("cp.async.commit_group;\n" ::: "memory");

        const int scur = kt - (kt / 3) * 3;
        const float* Asb = As + scur * TILEF;
        const float* Bsb = Bs + scur * TILEF;

#pragma unroll
        for (int ks = 0; ks < 4; ks++) {
            const int k0 = ks * 8;
            uint32_t af[4][4], bf[4][2];
#pragma unroll
            for (int mf = 0; mf < 4; mf++) {
                const float* ab = Asb + (wm0 + mf * 16 + ly) * ASTR + k0 + lx;
                af[mf][0] = f2tf(ab[0]);
                af[mf][1] = f2tf(ab[8 * ASTR]);
                af[mf][2] = f2tf(ab[4]);
                af[mf][3] = f2tf(ab[8 * ASTR + 4]);
            }
#pragma unroll
            for (int nf = 0; nf < 4; nf++) {
                const float* bb = Bsb + (wn0 + nf * 8 + ly) * ASTR + k0 + lx;
                bf[nf][0] = f2tf(bb[0]);
                bf[nf][1] = f2tf(bb[4]);
            }
#pragma unroll
            for (int mf = 0; mf < 4; mf++)
#pragma unroll
                for (int nf = 0; nf < 4; nf++)
                    asm volatile(
                        "mma.sync.aligned.m16n8k8.row.col.f32.tf32.tf32.f32 "
                        "{%0,%1,%2,%3}, {%4,%5,%6,%7}, {%8,%9}, {%0,%1,%2,%3};"
                        : "+f"(c[mf][nf][0]), "+f"(c[mf][nf][1]),
                          "+f"(c[mf][nf][2]), "+f"(c[mf][nf][3])
                        : "r"(af[mf][0]), "r"(af[mf][1]),
                          "r"(af[mf][2]), "r"(af[mf][3]),
                          "r"(bf[nf][0]), "r"(bf[nf][1]));
        }
    }
    asm volatile("cp.async.wait_group 0;\n" ::: "memory");

#pragma unroll
    for (int mf = 0; mf < 4; mf++) {
        const int r0 = m0 + wm0 + mf * 16 + ly;
#pragma unroll
        for (int nf = 0; nf < 4; nf++) {
            const int cb = n0 + wn0 + nf * 8 + lx * 2;
            float2 bv = *(const float2*)&bias[cb];
            float2 v0 = make_float2(c[mf][nf][0] + bv.x, c[mf][nf][1] + bv.y);
            float2 v1 = make_float2(c[mf][nf][2] + bv.x, c[mf][nf][3] + bv.y);
            if (mode == 0) {
                const int sec = cb >> 10;
                const int h   = (cb & 1023) >> 6;
                const int dh0 = cb & 63;
                float* dst = (sec == 0) ? g_q : (sec == 1) ? g_k : g_v;
                const int bb0 = r0 >> 11, ss0 = r0 & 2047;
                const int bb1 = (r0 + 8) >> 11, ss1 = (r0 + 8) & 2047;
                *(float2*)&dst[(((size_t)(bb0 * HH_ + h)) * SS_ + ss0) * DH_ + dh0] = v0;
                *(float2*)&dst[(((size_t)(bb1 * HH_ + h)) * SS_ + ss1) * DH_ + dh0] = v1;
            } else {
                *(float2*)&Cout[(size_t)r0 * Ntot + cb] = v0;
                *(float2*)&Cout[(size_t)(r0 + 8) * Ntot + cb] = v1;
            }
        }
    }
}

// ============================================================================
// Fused attention, 512 threads (16 warps) per block = (b, h, 16-query tile).
//   scores: 2 rows x 4 cols per thread; PV: 16-warp key split.
// ============================================================================
#define PSW 2052
#define KSW 260
#define QSW 20
#define TKEY 256
#define ATTN_SMEM_FLOATS (16*PSW + 64*KSW + 64*QSW + 16*64 + 16)
#define ATTN_SMEM_BYTES  (ATTN_SMEM_FLOATS * 4)

__global__ __launch_bounds__(512, 1)
void attn_kernel(const float* __restrict__ amask, float* __restrict__ attw)
{
    extern __shared__ __align__(16) float sm[];
    float* Ps  = sm;                    // 16 x PSW
    float* KsT = sm + 16 * PSW;         // 64 x KSW
    float* QsT = KsT + 64 * KSW;        // 64 x QSW
    float* red = QsT + 64 * QSW;        // 16 x 64
    float* inv = red + 16 * 64;         // 16

    const int t  = threadIdx.x;
    const int qt = blockIdx.x, h = blockIdx.y, b = blockIdx.z;
    const int q0 = qt * 16;
    const size_t bh = (size_t)(b * HH_ + h);
    const float* Qp = g_q + bh * SS_ * DH_;
    const float* Kp = g_k + bh * SS_ * DH_;
    const float* Vp = g_v + bh * SS_ * DH_;

    // ---- load Q tile transposed (first 256 threads) ----
    if (t < 256) {
        int r = t >> 4, dq = t & 15;
        float4 q4 = *(const float4*)&Qp[(size_t)(q0 + r) * DH_ + dq * 4];
        QsT[(dq * 4 + 0) * QSW + r] = q4.x;
        QsT[(dq * 4 + 1) * QSW + r] = q4.y;
        QsT[(dq * 4 + 2) * QSW + r] = q4.z;
        QsT[(dq * 4 + 3) * QSW + r] = q4.w;
    }

    const int num_kt = (q0 + 15) / TKEY + 1;
    const int rg = t >> 6, cg = t & 63;       // 2 rows x 4 cols per thread
    float rsum[2] = {0.f, 0.f};

    for (int kt = 0; kt < num_kt; kt++) {
        const int j0 = kt * TKEY;
        if (kt) __syncthreads();
        // ---- load K tile transposed: 512 threads, 4x4 micro-transpose ----
        {
            int jb = t >> 3, dq = t & 7;
            const float* kb = Kp + (size_t)(j0 + jb * 4) * DH_;
#pragma unroll
            for (int p = 0; p < 2; p++) {
                int dbase = (p * 8 + dq) * 4;
                float4 r0 = *(const float4*)&kb[0 * DH_ + dbase];
                float4 r1 = *(const float4*)&kb[1 * DH_ + dbase];
                float4 r2 = *(const float4*)&kb[2 * DH_ + dbase];
                float4 r3 = *(const float4*)&kb[3 * DH_ + dbase];
                *(float4*)&KsT[(dbase + 0) * KSW + jb * 4] = make_float4(r0.x, r1.x, r2.x, r3.x);
                *(float4*)&KsT[(dbase + 1) * KSW + jb * 4] = make_float4(r0.y, r1.y, r2.y, r3.y);
                *(float4*)&KsT[(dbase + 2) * KSW + jb * 4] = make_float4(r0.z, r1.z, r2.z, r3.z);
                *(float4*)&KsT[(dbase + 3) * KSW + jb * 4] = make_float4(r0.w, r1.w, r2.w, r3.w);
            }
        }
        __syncthreads();

        // ---- scores 2x4 register tile over d=64 ----
        float acc[2][4];
#pragma unroll
        for (int i = 0; i < 2; i++)
#pragma unroll
            for (int j = 0; j < 4; j++) acc[i][j] = 0.f;

#pragma unroll 8
        for (int d = 0; d < 64; d++) {
            float2 a2 = *(const float2*)&QsT[d * QSW + rg * 2];
            float4 b4 = *(const float4*)&KsT[d * KSW + cg * 4];
            float av[2] = {a2.x, a2.y};
            float bv[4] = {b4.x, b4.y, b4.z, b4.w};
#pragma unroll
            for (int i = 0; i < 2; i++)
#pragma unroll
                for (int j = 0; j < 4; j++)
                    acc[i][j] += av[i] * bv[j];
        }

        // ---- mask + exp + stash unnormalized e in Ps ----
        float4 am4 = *(const float4*)&amask[b * SS_ + j0 + cg * 4];
        float amv[4] = {am4.x, am4.y, am4.z, am4.w};
#pragma unroll
        for (int i = 0; i < 2; i++) {
            int qg = q0 + rg * 2 + i;
            float4 ev;
            float* e = (float*)&ev;
#pragma unroll
            for (int k2 = 0; k2 < 4; k2++) {
                int jg = j0 + cg * 4 + k2;
                float v = (jg <= qg) ? __expf(acc[i][k2] * 0.125f + amv[k2]) : 0.f;
                e[k2] = v;
                rsum[i] += v;
            }
            *(float4*)&Ps[(rg * 2 + i) * PSW + j0 + cg * 4] = ev;
        }
    }

    // ---- row-sum reduction -> inv[r] ----
#pragma unroll
    for (int i = 0; i < 2; i++) red[(rg * 2 + i) * 64 + cg] = rsum[i];
    __syncthreads();
    if (t < 256) {
        int r = t >> 4, x = t & 15;
        float s = red[r * 64 + x] + red[r * 64 + x + 16] +
                  red[r * 64 + x + 32] + red[r * 64 + x + 48];
        s += __shfl_down_sync(0xffffffffu, s, 8, 16);
        s += __shfl_down_sync(0xffffffffu, s, 4, 16);
        s += __shfl_down_sync(0xffffffffu, s, 2, 16);
        s += __shfl_down_sync(0xffffffffu, s, 1, 16);
        if (x == 0) inv[r] = 1.0f / s;
    }
    __syncthreads();

    // ---- write normalized P (zeros beyond causal reach) ----
    {
        int r = t >> 5, x = t & 31;
        float invr = inv[r];
        float* orow = attw + ((bh * SS_) + q0 + r) * (size_t)SS_;
        const int JMAX = num_kt * TKEY;
#pragma unroll 4
        for (int it = 0; it < 16; it++) {
            int col = it * 128 + x * 4;
            float4 v;
            if (col < JMAX) {
                float4 p = *(const float4*)&Ps[r * PSW + col];
                v = make_float4(p.x * invr, p.y * invr, p.z * invr, p.w * invr);
            } else {
                v = make_float4(0.f, 0.f, 0.f, 0.f);
            }
            *(float4*)&orow[col] = v;
        }
    }

    // ---- PV: O[16][64] = (unnormalized P) @ V, 16-warp key split ----
    {
        int w = t >> 5, lane = t & 31;
        int rg2 = lane >> 3, cg2 = lane & 7;
        float o[4][8];
#pragma unroll
        for (int k2 = 0; k2 < 4; k2++)
#pragma unroll
            for (int c = 0; c < 8; c++) o[k2][c] = 0.f;

        const int num_jt = num_kt * 4;        // 64-wide key tiles
        for (int jt = w; jt < num_jt; jt += 16) {
            const int jb0 = jt * 64;
#pragma unroll 4
            for (int jj = 0; jj < 64; jj++) {
                int j = jb0 + jj;
                float4 v0 = *(const float4*)&Vp[(size_t)j * DH_ + cg2 * 8];
                float4 v1 = *(const float4*)&Vp[(size_t)j * DH_ + cg2 * 8 + 4];
                float vv[8] = {v0.x, v0.y, v0.z, v0.w, v1.x, v1.y, v1.z, v1.w};
                float pp[4] = {Ps[(rg2 + 0) * PSW + j],  Ps[(rg2 + 4) * PSW + j],
                               Ps[(rg2 + 8) * PSW + j],  Ps[(rg2 + 12) * PSW + j]};
#pragma unroll
                for (int k2 = 0; k2 < 4; k2++)
#pragma unroll
                    for (int c = 0; c < 8; c++)
                        o[k2][c] += pp[k2] * vv[c];
            }
        }

        // cross-warp reduce (reuse KsT region: 16 x 1024 floats = 64KB <= 66.5KB)
        float* rb = KsT;
#pragma unroll
        for (int k2 = 0; k2 < 4; k2++) {
            *(float4*)&rb[w * 1024 + (rg2 + 4 * k2) * 64 + cg2 * 8] =
                make_float4(o[k2][0], o[k2][1], o[k2][2], o[k2][3]);
            *(float4*)&rb[w * 1024 + (rg2 + 4 * k2) * 64 + cg2 * 8 + 4] =
                make_float4(o[k2][4], o[k2][5], o[k2][6], o[k2][7]);
        }
        __syncthreads();
        {
            int r = t >> 5, c = (t & 31) * 2;
            float invr = inv[r];
            float2 s = make_float2(0.f, 0.f);
#pragma unroll
            for (int w2 = 0; w2 < 16; w2++) {
                float2 x2 = *(const float2*)&rb[w2 * 1024 + r * 64 + c];
                s.x += x2.x; s.y += x2.y;
            }
            s.x *= invr; s.y *= invr;
            *(float2*)&g_att[((size_t)(b * SS_) + q0 + r) * DD_ + h * 64 + c] = s;
        }
    }
}

// ============================================================================
extern "C" void kernel_launch(void* const* d_in, const int* in_sizes, int n_in,
                              void* d_out, int out_size)
{
    (void)in_sizes; (void)n_in; (void)out_size;
    const float* x     = (const float*)d_in[0];
    const float* amask = (const float*)d_in[1];
    const float* W_in  = (const float*)d_in[2];
    const float* b_in  = (const float*)d_in[3];
    const float* W_out = (const float*)d_in[4];
    const float* b_out = (const float*)d_in[5];

    float* out  = (float*)d_out;
    float* attw = out + (size_t)BB_ * SS_ * DD_;   // tuple order: (out, attn_weights)

    cudaFuncSetAttribute(attn_kernel, cudaFuncAttributeMaxDynamicSharedMemorySize,
                         ATTN_SMEM_BYTES);
    cudaFuncSetAttribute(mma_gemm, cudaFuncAttributeMaxDynamicSharedMemorySize,
                         GSMEM_BYTES);

    // 0) transpose weights into K-major [N,K] scratch
    transpose_kernel<<<dim3(96, 32), dim3(32, 8)>>>(W_in, 3072, 0);
    transpose_kernel<<<dim3(32, 32), dim3(32, 8)>>>(W_out, 1024, 3072 * 1024);

    // 1) QKV projection (TF32 mma.sync) -> g_q/g_k/g_v
    mma_gemm<<<dim3(24, 64), 256, GSMEM_BYTES>>>(x, 0, b_in, nullptr, 3072, 0);

    // 2) attention (512 threads): writes attn_weights (d_out tail) and g_att
    attn_kernel<<<dim3(SS_ / 16, HH_, BB_), 512, ATTN_SMEM_BYTES>>>(amask, attw);

    // 3) output projection (TF32 mma.sync) -> d_out head
    mma_gemm<<<dim3(8, 64), 256, GSMEM_BYTES>>>(nullptr, 3072 * 1024, b_out, out, 1024, 1);
}

// round 13
// speedup vs baseline: 1.2128x; 1.2128x over previous
#include <cuda_runtime.h>
#include <math.h>
#include <stdint.h>

#define BB_ 4
#define SS_ 2048
#define DD_ 1024
#define HH_ 16
#define DH_ 64

// ---------------- scratch (device globals: allocation-free) ----------------
__device__ float g_q[(size_t)BB_ * HH_ * SS_ * DH_];   // 33.5 MB
__device__ float g_k[(size_t)BB_ * HH_ * SS_ * DH_];
__device__ float g_v[(size_t)BB_ * HH_ * SS_ * DH_];
__device__ float g_att[(size_t)BB_ * SS_ * DD_];       // merged-head attention output
__device__ float g_wt[(size_t)3072 * 1024 + 1024 * 1024];  // W_in^T then W_out^T ([N,K])

// =============================== PTX helpers ===============================
__device__ __forceinline__ uint32_t smem_u32(const void* p) {
    uint32_t a;
    asm("{ .reg .u64 t; cvta.to.shared.u64 t, %1; cvt.u32.u64 %0, t; }"
        : "=r"(a) : "l"(p));
    return a;
}

__device__ __forceinline__ uint32_t f2tf(float x) {
    uint32_t r;
    asm("cvt.rna.tf32.f32 %0, %1;" : "=r"(r) : "f"(x));
    return r;
}

#define MMA_TF32(c0,c1,c2,c3, a0,a1,a2,a3, b0,b1) \
    asm volatile( \
        "mma.sync.aligned.m16n8k8.row.col.f32.tf32.tf32.f32 " \
        "{%0,%1,%2,%3}, {%4,%5,%6,%7}, {%8,%9}, {%0,%1,%2,%3};" \
        : "+f"(c0), "+f"(c1), "+f"(c2), "+f"(c3) \
        : "r"(a0), "r"(a1), "r"(a2), "r"(a3), "r"(b0), "r"(b1))

// ============================================================================
// W transpose: Wt[n*1024 + k] = W[k*N + n]
// ============================================================================
__global__ void transpose_kernel(const float* __restrict__ W, int N, int out_off)
{
    __shared__ float tile[32][33];
    int n0 = blockIdx.x * 32, k0 = blockIdx.y * 32;
    int tx = threadIdx.x, ty = threadIdx.y;   // 32 x 8
#pragma unroll
    for (int i = 0; i < 32; i += 8)
        tile[ty + i][tx] = W[(size_t)(k0 + ty + i) * N + n0 + tx];
    __syncthreads();
    float* Wt = g_wt + out_off;
#pragma unroll
    for (int i = 0; i < 32; i += 8)
        Wt[(size_t)(n0 + ty + i) * 1024 + k0 + tx] = tile[tx][ty + i];
}

// ============================================================================
// TF32 mma.sync GEMM (unchanged, passing): C[M,N] = A[M,1024] @ W[1024,N] + b
// ============================================================================
#define ASTR 36
#define TILEF (128 * ASTR)
#define GSTAGES 3
#define GSMEM_BYTES (GSTAGES * 2 * TILEF * 4)   // 110,592

__device__ __forceinline__ void ld_tile(const float* __restrict__ src, int row0,
                                        int k0, float* dst, int t)
{
#pragma unroll
    for (int i = 0; i < 4; i++) {
        int idx = t + i * 256;
        int r = idx >> 3, c = idx & 7;
        const float* g = src + (size_t)(row0 + r) * 1024 + k0 + c * 4;
        uint32_t d = smem_u32(dst + r * ASTR + c * 4);
        asm volatile("cp.async.cg.shared.global [%0], [%1], 16;\n"
                     :: "r"(d), "l"(g));
    }
}

__global__ __launch_bounds__(256)
void mma_gemm(const float* __restrict__ A_, int wt_off,
              const float* __restrict__ bias, float* __restrict__ Cout,
              int Ntot, int mode)
{
    extern __shared__ __align__(16) float sm[];
    const float* A  = (mode == 1) ? g_att : A_;
    const float* Bt = g_wt + wt_off;
    float* As = sm;
    float* Bs = sm + GSTAGES * TILEF;

    const int t = threadIdx.x, wid = t >> 5, lane = t & 31;
    const int n0 = blockIdx.x * 128, m0 = blockIdx.y * 128;
    const int wm0 = (wid >> 2) * 64, wn0 = (wid & 3) * 32;
    const int ly = lane >> 2, lx = lane & 3;

    float c[4][4][4];
#pragma unroll
    for (int mf = 0; mf < 4; mf++)
#pragma unroll
        for (int nf = 0; nf < 4; nf++)
#pragma unroll
            for (int i = 0; i < 4; i++) c[mf][nf][i] = 0.f;

#pragma unroll
    for (int j = 0; j < 2; j++) {
        ld_tile(A,  m0, j * 32, As + j * TILEF, t);
        ld_tile(Bt, n0, j * 32, Bs + j * TILEF, t);
        asm volatile("cp.async.commit_group;\n" ::: "memory");
    }

    for (int kt = 0; kt < 32; kt++) {
        asm volatile("cp.async.wait_group 1;\n" ::: "memory");
        __syncthreads();

        int j = kt + 2;
        if (j < 32) {
            int s = j - (j / 3) * 3;
            ld_tile(A,  m0, j * 32, As + s * TILEF, t);
            ld_tile(Bt, n0, j * 32, Bs + s * TILEF, t);
        }
        asm volatile("cp.async.commit_group;\n" ::: "memory");

        const int scur = kt - (kt / 3) * 3;
        const float* Asb = As + scur * TILEF;
        const float* Bsb = Bs + scur * TILEF;

#pragma unroll
        for (int ks = 0; ks < 4; ks++) {
            const int k0 = ks * 8;
            uint32_t af[4][4], bf[4][2];
#pragma unroll
            for (int mf = 0; mf < 4; mf++) {
                const float* ab = Asb + (wm0 + mf * 16 + ly) * ASTR + k0 + lx;
                af[mf][0] = f2tf(ab[0]);
                af[mf][1] = f2tf(ab[8 * ASTR]);
                af[mf][2] = f2tf(ab[4]);
                af[mf][3] = f2tf(ab[8 * ASTR + 4]);
            }
#pragma unroll
            for (int nf = 0; nf < 4; nf++) {
                const float* bb = Bsb + (wn0 + nf * 8 + ly) * ASTR + k0 + lx;
                bf[nf][0] = f2tf(bb[0]);
                bf[nf][1] = f2tf(bb[4]);
            }
#pragma unroll
            for (int mf = 0; mf < 4; mf++)
#pragma unroll
                for (int nf = 0; nf < 4; nf++)
                    MMA_TF32(c[mf][nf][0], c[mf][nf][1], c[mf][nf][2], c[mf][nf][3],
                             af[mf][0], af[mf][1], af[mf][2], af[mf][3],
                             bf[nf][0], bf[nf][1]);
        }
    }
    asm volatile("cp.async.wait_group 0;\n" ::: "memory");

#pragma unroll
    for (int mf = 0; mf < 4; mf++) {
        const int r0 = m0 + wm0 + mf * 16 + ly;
#pragma unroll
        for (int nf = 0; nf < 4; nf++) {
            const int cb = n0 + wn0 + nf * 8 + lx * 2;
            float2 bv = *(const float2*)&bias[cb];
            float2 v0 = make_float2(c[mf][nf][0] + bv.x, c[mf][nf][1] + bv.y);
            float2 v1 = make_float2(c[mf][nf][2] + bv.x, c[mf][nf][3] + bv.y);
            if (mode == 0) {
                const int sec = cb >> 10;
                const int h   = (cb & 1023) >> 6;
                const int dh0 = cb & 63;
                float* dst = (sec == 0) ? g_q : (sec == 1) ? g_k : g_v;
                const int bb0 = r0 >> 11, ss0 = r0 & 2047;
                const int bb1 = (r0 + 8) >> 11, ss1 = (r0 + 8) & 2047;
                *(float2*)&dst[(((size_t)(bb0 * HH_ + h)) * SS_ + ss0) * DH_ + dh0] = v0;
                *(float2*)&dst[(((size_t)(bb1 * HH_ + h)) * SS_ + ss1) * DH_ + dh0] = v1;
            } else {
                *(float2*)&Cout[(size_t)r0 * Ntot + cb] = v0;
                *(float2*)&Cout[(size_t)(r0 + 8) * Ntot + cb] = v1;
            }
        }
    }
}

// ============================================================================
// Fused attention, 512 threads (16 warps) per block = (b, h, 16-query tile).
//   Scores: split-TF32 mma.sync (hi*hi + hi*lo + lo*hi ~= fp32 accuracy),
//           K consumed as-stored [j][d] (mma col operand) via cp.async,
//           double-buffered 128-key tiles.
//   PV: fp32 FFMA, 16-warp key split (unchanged numerics).
// ============================================================================
#define TKEY 128
#define PSW 2052
#define KPAD 68
// floats: Ps 16*2052 + K 2*128*68 + Q 16*68 + red 16*16 + inv 16
#define ATTN_SMEM_FLOATS (16*PSW + 2*TKEY*KPAD + 16*KPAD + 256 + 16)
#define ATTN_SMEM_BYTES  (ATTN_SMEM_FLOATS * 4)   // 206,400

// Full 128x64 K tile via cp.async: 2048 float4 chunks, 512 threads x 4.
__device__ __forceinline__ void ld_ktile(const float* __restrict__ Kp, int row0,
                                         float* dst, int t)
{
#pragma unroll
    for (int i = 0; i < 4; i++) {
        int idx = t + i * 512;
        int r = idx >> 4, c = (idx & 15) * 4;
        uint32_t d = smem_u32(dst + r * KPAD + c);
        asm volatile("cp.async.cg.shared.global [%0], [%1], 16;\n"
                     :: "r"(d), "l"(Kp + (size_t)(row0 + r) * DH_ + c));
    }
}

__global__ __launch_bounds__(512, 1)
void attn_kernel(const float* __restrict__ amask, float* __restrict__ attw)
{
    extern __shared__ __align__(16) float sm[];
    float* Ps  = sm;                          // 16 x PSW
    float* Ks  = sm + 16 * PSW;               // 2 x 128 x KPAD  (K as-stored)
    float* Qs  = Ks + 2 * TKEY * KPAD;         // 16 x KPAD
    float* red = Qs + 16 * KPAD;               // 16 x 16
    float* inv = red + 256;                    // 16

    const int t  = threadIdx.x;
    const int qt = blockIdx.x, h = blockIdx.y, b = blockIdx.z;
    const int q0 = qt * 16;
    const size_t bh = (size_t)(b * HH_ + h);
    const float* Qp = g_q + bh * SS_ * DH_;
    const float* Kp = g_k + bh * SS_ * DH_;
    const float* Vp = g_v + bh * SS_ * DH_;

    const int w = t >> 5, lane = t & 31;
    const int ly = lane >> 2, lx = lane & 3;

    // ---- load Q tile [16][64] into Qs: 256 chunks, 256 threads x 1 ----
    if (t < 256) {
        int r = t >> 4, c = (t & 15) * 4;
        float4 q4 = *(const float4*)&Qp[(size_t)(q0 + r) * DH_ + c];
        *(float4*)&Qs[r * KPAD + c] = q4;
    }

    const int num_kt = (q0 + 15) / TKEY + 1;

    // ---- prologue: cp.async K tile 0 into buffer 0 ----
    ld_ktile(Kp, 0, Ks, t);
    asm volatile("cp.async.commit_group;\n" ::: "memory");
    __syncthreads();   // Qs visible to all

    // ---- hoist Q a-fragments (hi/lo split) into registers ----
    uint32_t ah[8][4], al[8][4];
#pragma unroll
    for (int ks = 0; ks < 8; ks++) {
        float a0 = Qs[ly * KPAD + ks * 8 + lx];
        float a1 = Qs[(ly + 8) * KPAD + ks * 8 + lx];
        float a2 = Qs[ly * KPAD + ks * 8 + lx + 4];
        float a3 = Qs[(ly + 8) * KPAD + ks * 8 + lx + 4];
        ah[ks][0] = f2tf(a0); al[ks][0] = f2tf(a0 - __uint_as_float(ah[ks][0]));
        ah[ks][1] = f2tf(a1); al[ks][1] = f2tf(a1 - __uint_as_float(ah[ks][1]));
        ah[ks][2] = f2tf(a2); al[ks][2] = f2tf(a2 - __uint_as_float(ah[ks][2]));
        ah[ks][3] = f2tf(a3); al[ks][3] = f2tf(a3 - __uint_as_float(ah[ks][3]));
    }

    float rsum0 = 0.f, rsum1 = 0.f;

    for (int kt = 0; kt < num_kt; kt++) {
        const int j0 = kt * TKEY;
        // prefetch next tile into the other buffer
        if (kt + 1 < num_kt) {
            ld_ktile(Kp, j0 + TKEY, Ks + ((kt + 1) & 1) * TKEY * KPAD, t);
            asm volatile("cp.async.commit_group;\n" ::: "memory");
            asm volatile("cp.async.wait_group 1;\n" ::: "memory");
        } else {
            asm volatile("cp.async.wait_group 0;\n" ::: "memory");
        }
        __syncthreads();   // tile kt visible; prev compute done before overwrite

        const float* Kb = Ks + (kt & 1) * TKEY * KPAD;
        float c0 = 0.f, c1 = 0.f, c2 = 0.f, c3 = 0.f;

#pragma unroll
        for (int ks = 0; ks < 8; ks++) {
            float b0f = Kb[(w * 8 + ly) * KPAD + ks * 8 + lx];
            float b1f = Kb[(w * 8 + ly) * KPAD + ks * 8 + lx + 4];
            uint32_t bh0 = f2tf(b0f), bl0 = f2tf(b0f - __uint_as_float(bh0));
            uint32_t bh1 = f2tf(b1f), bl1 = f2tf(b1f - __uint_as_float(bh1));
            MMA_TF32(c0, c1, c2, c3, ah[ks][0], ah[ks][1], ah[ks][2], ah[ks][3], bh0, bh1);
            MMA_TF32(c0, c1, c2, c3, ah[ks][0], ah[ks][1], ah[ks][2], ah[ks][3], bl0, bl1);
            MMA_TF32(c0, c1, c2, c3, al[ks][0], al[ks][1], al[ks][2], al[ks][3], bh0, bh1);
        }

        // ---- mask + exp + stash unnormalized e in Ps ----
        const int col = j0 + w * 8 + 2 * lx;       // this thread's 2 columns
        const float am0 = amask[b * SS_ + col];
        const float am1 = amask[b * SS_ + col + 1];
        const int qg0 = q0 + ly, qg1 = q0 + ly + 8;
        float e0 = (col     <= qg0) ? __expf(c0 * 0.125f + am0) : 0.f;
        float e1 = (col + 1 <= qg0) ? __expf(c1 * 0.125f + am1) : 0.f;
        float e2 = (col     <= qg1) ? __expf(c2 * 0.125f + am0) : 0.f;
        float e3 = (col + 1 <= qg1) ? __expf(c3 * 0.125f + am1) : 0.f;
        rsum0 += e0 + e1;
        rsum1 += e2 + e3;
        *(float2*)&Ps[ly * PSW + col]       = make_float2(e0, e1);
        *(float2*)&Ps[(ly + 8) * PSW + col] = make_float2(e2, e3);

        __syncthreads();   // all reads of Kb done before its buffer is refilled
    }

    // ---- row-sum reduction -> inv[r] ----
    rsum0 += __shfl_xor_sync(0xffffffffu, rsum0, 1);
    rsum0 += __shfl_xor_sync(0xffffffffu, rsum0, 2);
    rsum1 += __shfl_xor_sync(0xffffffffu, rsum1, 1);
    rsum1 += __shfl_xor_sync(0xffffffffu, rsum1, 2);
    if (lx == 0) {
        red[ly * 16 + w]       = rsum0;
        red[(ly + 8) * 16 + w] = rsum1;
    }
    __syncthreads();
    if (t < 256) {
        int r = t >> 4, x = t & 15;
        float s = red[r * 16 + x];
        s += __shfl_down_sync(0xffffffffu, s, 8, 16);
        s += __shfl_down_sync(0xffffffffu, s, 4, 16);
        s += __shfl_down_sync(0xffffffffu, s, 2, 16);
        s += __shfl_down_sync(0xffffffffu, s, 1, 16);
        if (x == 0) inv[r] = 1.0f / s;
    }
    __syncthreads();

    // ---- write normalized P (zeros beyond causal reach) ----
    {
        int r = t >> 5, x = t & 31;
        float invr = inv[r];
        float* orow = attw + ((bh * SS_) + q0 + r) * (size_t)SS_;
        const int JMAX = num_kt * TKEY;
#pragma unroll 4
        for (int it = 0; it < 16; it++) {
            int col = it * 128 + x * 4;
            float4 v;
            if (col < JMAX) {
                float4 p = *(const float4*)&Ps[r * PSW + col];
                v = make_float4(p.x * invr, p.y * invr, p.z * invr, p.w * invr);
            } else {
                v = make_float4(0.f, 0.f, 0.f, 0.f);
            }
            *(float4*)&orow[col] = v;
        }
    }

    // ---- PV: O[16][64] = (unnormalized P) @ V, 16-warp key split ----
    {
        int rg2 = lane >> 3, cg2 = lane & 7;
        float o[4][8];
#pragma unroll
        for (int k2 = 0; k2 < 4; k2++)
#pragma unroll
            for (int c = 0; c < 8; c++) o[k2][c] = 0.f;

        const int num_jt = num_kt * 2;        // 64-wide key tiles
        for (int jt = w; jt < num_jt; jt += 16) {
            const int jb0 = jt * 64;
#pragma unroll 4
            for (int jj = 0; jj < 64; jj++) {
                int j = jb0 + jj;
                float4 v0 = *(const float4*)&Vp[(size_t)j * DH_ + cg2 * 8];
                float4 v1 = *(const float4*)&Vp[(size_t)j * DH_ + cg2 * 8 + 4];
                float vv[8] = {v0.x, v0.y, v0.z, v0.w, v1.x, v1.y, v1.z, v1.w};
                float pp[4] = {Ps[(rg2 + 0) * PSW + j],  Ps[(rg2 + 4) * PSW + j],
                               Ps[(rg2 + 8) * PSW + j],  Ps[(rg2 + 12) * PSW + j]};
#pragma unroll
                for (int k2 = 0; k2 < 4; k2++)
#pragma unroll
                    for (int c = 0; c < 8; c++)
                        o[k2][c] += pp[k2] * vv[c];
            }
        }

        // cross-warp reduce (reuse Ks region: 16 x 1024 floats = 64KB <= 69.6KB)
        float* rb = Ks;
#pragma unroll
        for (int k2 = 0; k2 < 4; k2++) {
            *(float4*)&rb[w * 1024 + (rg2 + 4 * k2) * 64 + cg2 * 8] =
                make_float4(o[k2][0], o[k2][1], o[k2][2], o[k2][3]);
            *(float4*)&rb[w * 1024 + (rg2 + 4 * k2) * 64 + cg2 * 8 + 4] =
                make_float4(o[k2][4], o[k2][5], o[k2][6], o[k2][7]);
        }
        __syncthreads();
        {
            int r = t >> 5, c = (t & 31) * 2;
            float invr = inv[r];
            float2 s = make_float2(0.f, 0.f);
#pragma unroll
            for (int w2 = 0; w2 < 16; w2++) {
                float2 x2 = *(const float2*)&rb[w2 * 1024 + r * 64 + c];
                s.x += x2.x; s.y += x2.y;
            }
            s.x *= invr; s.y *= invr;
            *(float2*)&g_att[((size_t)(b * SS_) + q0 + r) * DD_ + h * 64 + c] = s;
        }
    }
}

// ============================================================================
extern "C" void kernel_launch(void* const* d_in, const int* in_sizes, int n_in,
                              void* d_out, int out_size)
{
    (void)in_sizes; (void)n_in; (void)out_size;
    const float* x     = (const float*)d_in[0];
    const float* amask = (const float*)d_in[1];
    const float* W_in  = (const float*)d_in[2];
    const float* b_in  = (const float*)d_in[3];
    const float* W_out = (const float*)d_in[4];
    const float* b_out = (const float*)d_in[5];

    float* out  = (float*)d_out;
    float* attw = out + (size_t)BB_ * SS_ * DD_;   // tuple order: (out, attn_weights)

    cudaFuncSetAttribute(attn_kernel, cudaFuncAttributeMaxDynamicSharedMemorySize,
                         ATTN_SMEM_BYTES);
    cudaFuncSetAttribute(mma_gemm, cudaFuncAttributeMaxDynamicSharedMemorySize,
                         GSMEM_BYTES);

    // 0) transpose weights into K-major [N,K] scratch
    transpose_kernel<<<dim3(96, 32), dim3(32, 8)>>>(W_in, 3072, 0);
    transpose_kernel<<<dim3(32, 32), dim3(32, 8)>>>(W_out, 1024, 3072 * 1024);

    // 1) QKV projection (TF32 mma.sync) -> g_q/g_k/g_v
    mma_gemm<<<dim3(24, 64), 256, GSMEM_BYTES>>>(x, 0, b_in, nullptr, 3072, 0);

    // 2) attention (split-TF32 mma scores + fp32 PV)
    attn_kernel<<<dim3(SS_ / 16, HH_, BB_), 512, ATTN_SMEM_BYTES>>>(amask, attw);

    // 3) output projection (TF32 mma.sync) -> d_out head
    mma_gemm<<<dim3(8, 64), 256, GSMEM_BYTES>>>(nullptr, 3072 * 1024, b_out, out, 1024, 1);
}

// round 14
// speedup vs baseline: 1.4356x; 1.1836x over previous
#include <cuda_runtime.h>
#include <math.h>
#include <stdint.h>

#define BB_ 4
#define SS_ 2048
#define DD_ 1024
#define HH_ 16
#define DH_ 64

// ---------------- scratch (device globals: allocation-free) ----------------
__device__ float g_q[(size_t)BB_ * HH_ * SS_ * DH_];   // 33.5 MB
__device__ float g_k[(size_t)BB_ * HH_ * SS_ * DH_];
__device__ float g_v[(size_t)BB_ * HH_ * SS_ * DH_];
__device__ float g_att[(size_t)BB_ * SS_ * DD_];       // merged-head attention output
__device__ float g_wt[(size_t)3072 * 1024 + 1024 * 1024];  // W_in^T then W_out^T ([N,K])

// =============================== PTX helpers ===============================
__device__ __forceinline__ uint32_t smem_u32(const void* p) {
    uint32_t a;
    asm("{ .reg .u64 t; cvta.to.shared.u64 t, %1; cvt.u32.u64 %0, t; }"
        : "=r"(a) : "l"(p));
    return a;
}

__device__ __forceinline__ uint32_t f2tf(float x) {
    uint32_t r;
    asm("cvt.rna.tf32.f32 %0, %1;" : "=r"(r) : "f"(x));
    return r;
}

#define MMA_TF32(c0,c1,c2,c3, a0,a1,a2,a3, b0,b1) \
    asm volatile( \
        "mma.sync.aligned.m16n8k8.row.col.f32.tf32.tf32.f32 " \
        "{%0,%1,%2,%3}, {%4,%5,%6,%7}, {%8,%9}, {%0,%1,%2,%3};" \
        : "+f"(c0), "+f"(c1), "+f"(c2), "+f"(c3) \
        : "r"(a0), "r"(a1), "r"(a2), "r"(a3), "r"(b0), "r"(b1))

// ============================================================================
// W transpose: Wt[n*1024 + k] = W[k*N + n]
// ============================================================================
__global__ void transpose_kernel(const float* __restrict__ W, int N, int out_off)
{
    __shared__ float tile[32][33];
    int n0 = blockIdx.x * 32, k0 = blockIdx.y * 32;
    int tx = threadIdx.x, ty = threadIdx.y;   // 32 x 8
#pragma unroll
    for (int i = 0; i < 32; i += 8)
        tile[ty + i][tx] = W[(size_t)(k0 + ty + i) * N + n0 + tx];
    __syncthreads();
    float* Wt = g_wt + out_off;
#pragma unroll
    for (int i = 0; i < 32; i += 8)
        Wt[(size_t)(n0 + ty + i) * 1024 + k0 + tx] = tile[tx][ty + i];
}

// ============================================================================
// TF32 mma.sync GEMM (unchanged, passing): C[M,N] = A[M,1024] @ W[1024,N] + b
// ============================================================================
#define ASTR 36
#define TILEF (128 * ASTR)
#define GSTAGES 3
#define GSMEM_BYTES (GSTAGES * 2 * TILEF * 4)   // 110,592

__device__ __forceinline__ void ld_tile(const float* __restrict__ src, int row0,
                                        int k0, float* dst, int t)
{
#pragma unroll
    for (int i = 0; i < 4; i++) {
        int idx = t + i * 256;
        int r = idx >> 3, c = idx & 7;
        const float* g = src + (size_t)(row0 + r) * 1024 + k0 + c * 4;
        uint32_t d = smem_u32(dst + r * ASTR + c * 4);
        asm volatile("cp.async.cg.shared.global [%0], [%1], 16;\n"
                     :: "r"(d), "l"(g));
    }
}

__global__ __launch_bounds__(256)
void mma_gemm(const float* __restrict__ A_, int wt_off,
              const float* __restrict__ bias, float* __restrict__ Cout,
              int Ntot, int mode)
{
    extern __shared__ __align__(16) float sm[];
    const float* A  = (mode == 1) ? g_att : A_;
    const float* Bt = g_wt + wt_off;
    float* As = sm;
    float* Bs = sm + GSTAGES * TILEF;

    const int t = threadIdx.x, wid = t >> 5, lane = t & 31;
    const int n0 = blockIdx.x * 128, m0 = blockIdx.y * 128;
    const int wm0 = (wid >> 2) * 64, wn0 = (wid & 3) * 32;
    const int ly = lane >> 2, lx = lane & 3;

    float c[4][4][4];
#pragma unroll
    for (int mf = 0; mf < 4; mf++)
#pragma unroll
        for (int nf = 0; nf < 4; nf++)
#pragma unroll
            for (int i = 0; i < 4; i++) c[mf][nf][i] = 0.f;

#pragma unroll
    for (int j = 0; j < 2; j++) {
        ld_tile(A,  m0, j * 32, As + j * TILEF, t);
        ld_tile(Bt, n0, j * 32, Bs + j * TILEF, t);
        asm volatile("cp.async.commit_group;\n" ::: "memory");
    }

    for (int kt = 0; kt < 32; kt++) {
        asm volatile("cp.async.wait_group 1;\n" ::: "memory");
        __syncthreads();

        int j = kt + 2;
        if (j < 32) {
            int s = j - (j / 3) * 3;
            ld_tile(A,  m0, j * 32, As + s * TILEF, t);
            ld_tile(Bt, n0, j * 32, Bs + s * TILEF, t);
        }
        asm volatile("cp.async.commit_group;\n" ::: "memory");

        const int scur = kt - (kt / 3) * 3;
        const float* Asb = As + scur * TILEF;
        const float* Bsb = Bs + scur * TILEF;

#pragma unroll
        for (int ks = 0; ks < 4; ks++) {
            const int k0 = ks * 8;
            uint32_t af[4][4], bf[4][2];
#pragma unroll
            for (int mf = 0; mf < 4; mf++) {
                const float* ab = Asb + (wm0 + mf * 16 + ly) * ASTR + k0 + lx;
                af[mf][0] = f2tf(ab[0]);
                af[mf][1] = f2tf(ab[8 * ASTR]);
                af[mf][2] = f2tf(ab[4]);
                af[mf][3] = f2tf(ab[8 * ASTR + 4]);
            }
#pragma unroll
            for (int nf = 0; nf < 4; nf++) {
                const float* bb = Bsb + (wn0 + nf * 8 + ly) * ASTR + k0 + lx;
                bf[nf][0] = f2tf(bb[0]);
                bf[nf][1] = f2tf(bb[4]);
            }
#pragma unroll
            for (int mf = 0; mf < 4; mf++)
#pragma unroll
                for (int nf = 0; nf < 4; nf++)
                    MMA_TF32(c[mf][nf][0], c[mf][nf][1], c[mf][nf][2], c[mf][nf][3],
                             af[mf][0], af[mf][1], af[mf][2], af[mf][3],
                             bf[nf][0], bf[nf][1]);
        }
    }
    asm volatile("cp.async.wait_group 0;\n" ::: "memory");

#pragma unroll
    for (int mf = 0; mf < 4; mf++) {
        const int r0 = m0 + wm0 + mf * 16 + ly;
#pragma unroll
        for (int nf = 0; nf < 4; nf++) {
            const int cb = n0 + wn0 + nf * 8 + lx * 2;
            float2 bv = *(const float2*)&bias[cb];
            float2 v0 = make_float2(c[mf][nf][0] + bv.x, c[mf][nf][1] + bv.y);
            float2 v1 = make_float2(c[mf][nf][2] + bv.x, c[mf][nf][3] + bv.y);
            if (mode == 0) {
                const int sec = cb >> 10;
                const int h   = (cb & 1023) >> 6;
                const int dh0 = cb & 63;
                float* dst = (sec == 0) ? g_q : (sec == 1) ? g_k : g_v;
                const int bb0 = r0 >> 11, ss0 = r0 & 2047;
                const int bb1 = (r0 + 8) >> 11, ss1 = (r0 + 8) & 2047;
                *(float2*)&dst[(((size_t)(bb0 * HH_ + h)) * SS_ + ss0) * DH_ + dh0] = v0;
                *(float2*)&dst[(((size_t)(bb1 * HH_ + h)) * SS_ + ss1) * DH_ + dh0] = v1;
            } else {
                *(float2*)&Cout[(size_t)r0 * Ntot + cb] = v0;
                *(float2*)&Cout[(size_t)(r0 + 8) * Ntot + cb] = v1;
            }
        }
    }
}

// ============================================================================
// Fused attention, 512 threads (16 warps) per block = (b, h, 16-query tile).
//   Scores: split-TF32 mma.sync, K as-stored via cp.async, double-buffered.
//   PV:     split-TF32 mma.sync, V staged via cp.async into the (dead) K
//           region; warp w owns keys [j0+8w, j0+8w+8); cross-warp reduce.
// ============================================================================
#define TKEY 128
#define PSW 2052
#define KPAD 68
#define VPAD 72
#define VTILE (TKEY * VPAD)          // 9216 floats per V buffer
#define KVREG (2 * VTILE)            // 18432 floats (>= 2*128*68 for K)
// floats: Ps 16*2052 + KV 18432 + Q 16*68 + red 256 + inv 16
#define ATTN_SMEM_FLOATS (16*PSW + KVREG + 16*KPAD + 256 + 16)
#define ATTN_SMEM_BYTES  (ATTN_SMEM_FLOATS * 4)   // 210,496

// Full 128x64 K tile via cp.async (stride KPAD): 2048 chunks, 512 thr x 4.
__device__ __forceinline__ void ld_ktile(const float* __restrict__ Kp, int row0,
                                         float* dst, int t)
{
#pragma unroll
    for (int i = 0; i < 4; i++) {
        int idx = t + i * 512;
        int r = idx >> 4, c = (idx & 15) * 4;
        uint32_t d = smem_u32(dst + r * KPAD + c);
        asm volatile("cp.async.cg.shared.global [%0], [%1], 16;\n"
                     :: "r"(d), "l"(Kp + (size_t)(row0 + r) * DH_ + c));
    }
}

// Full 128x64 V tile via cp.async (stride VPAD).
__device__ __forceinline__ void ld_vtile(const float* __restrict__ Vp, int row0,
                                         float* dst, int t)
{
#pragma unroll
    for (int i = 0; i < 4; i++) {
        int idx = t + i * 512;
        int r = idx >> 4, c = (idx & 15) * 4;
        uint32_t d = smem_u32(dst + r * VPAD + c);
        asm volatile("cp.async.cg.shared.global [%0], [%1], 16;\n"
                     :: "r"(d), "l"(Vp + (size_t)(row0 + r) * DH_ + c));
    }
}

__global__ __launch_bounds__(512, 1)
void attn_kernel(const float* __restrict__ amask, float* __restrict__ attw)
{
    extern __shared__ __align__(16) float sm[];
    float* Ps  = sm;                          // 16 x PSW
    float* KV  = sm + 16 * PSW;               // K tiles / V tiles / reduce buf
    float* Qs  = KV + KVREG;                  // 16 x KPAD
    float* red = Qs + 16 * KPAD;              // 16 x 16
    float* inv = red + 256;                   // 16

    const int t  = threadIdx.x;
    const int qt = blockIdx.x, h = blockIdx.y, b = blockIdx.z;
    const int q0 = qt * 16;
    const size_t bh = (size_t)(b * HH_ + h);
    const float* Qp = g_q + bh * SS_ * DH_;
    const float* Kp = g_k + bh * SS_ * DH_;
    const float* Vp = g_v + bh * SS_ * DH_;

    const int w = t >> 5, lane = t & 31;
    const int ly = lane >> 2, lx = lane & 3;

    // ---- load Q tile [16][64] into Qs ----
    if (t < 256) {
        int r = t >> 4, c = (t & 15) * 4;
        float4 q4 = *(const float4*)&Qp[(size_t)(q0 + r) * DH_ + c];
        *(float4*)&Qs[r * KPAD + c] = q4;
    }

    const int num_kt = (q0 + 15) / TKEY + 1;

    // ---- prologue: cp.async K tile 0 ----
    ld_ktile(Kp, 0, KV, t);
    asm volatile("cp.async.commit_group;\n" ::: "memory");
    __syncthreads();   // Qs visible

    // ---- hoist Q a-fragments (hi/lo split) ----
    uint32_t ah[8][4], al[8][4];
#pragma unroll
    for (int ks = 0; ks < 8; ks++) {
        float a0 = Qs[ly * KPAD + ks * 8 + lx];
        float a1 = Qs[(ly + 8) * KPAD + ks * 8 + lx];
        float a2 = Qs[ly * KPAD + ks * 8 + lx + 4];
        float a3 = Qs[(ly + 8) * KPAD + ks * 8 + lx + 4];
        ah[ks][0] = f2tf(a0); al[ks][0] = f2tf(a0 - __uint_as_float(ah[ks][0]));
        ah[ks][1] = f2tf(a1); al[ks][1] = f2tf(a1 - __uint_as_float(ah[ks][1]));
        ah[ks][2] = f2tf(a2); al[ks][2] = f2tf(a2 - __uint_as_float(ah[ks][2]));
        ah[ks][3] = f2tf(a3); al[ks][3] = f2tf(a3 - __uint_as_float(ah[ks][3]));
    }

    float rsum0 = 0.f, rsum1 = 0.f;

    // =================== score phase ===================
    for (int kt = 0; kt < num_kt; kt++) {
        const int j0 = kt * TKEY;
        if (kt + 1 < num_kt) {
            ld_ktile(Kp, j0 + TKEY, KV + ((kt + 1) & 1) * VTILE, t);
            asm volatile("cp.async.commit_group;\n" ::: "memory");
            asm volatile("cp.async.wait_group 1;\n" ::: "memory");
        } else {
            asm volatile("cp.async.wait_group 0;\n" ::: "memory");
        }
        __syncthreads();

        const float* Kb = KV + (kt & 1) * VTILE;
        float c0 = 0.f, c1 = 0.f, c2 = 0.f, c3 = 0.f;

#pragma unroll
        for (int ks = 0; ks < 8; ks++) {
            float b0f = Kb[(w * 8 + ly) * KPAD + ks * 8 + lx];
            float b1f = Kb[(w * 8 + ly) * KPAD + ks * 8 + lx + 4];
            uint32_t bh0 = f2tf(b0f), bl0 = f2tf(b0f - __uint_as_float(bh0));
            uint32_t bh1 = f2tf(b1f), bl1 = f2tf(b1f - __uint_as_float(bh1));
            MMA_TF32(c0, c1, c2, c3, ah[ks][0], ah[ks][1], ah[ks][2], ah[ks][3], bh0, bh1);
            MMA_TF32(c0, c1, c2, c3, ah[ks][0], ah[ks][1], ah[ks][2], ah[ks][3], bl0, bl1);
            MMA_TF32(c0, c1, c2, c3, al[ks][0], al[ks][1], al[ks][2], al[ks][3], bh0, bh1);
        }

        const int col = j0 + w * 8 + 2 * lx;
        const float am0 = amask[b * SS_ + col];
        const float am1 = amask[b * SS_ + col + 1];
        const int qg0 = q0 + ly, qg1 = q0 + ly + 8;
        float e0 = (col     <= qg0) ? __expf(c0 * 0.125f + am0) : 0.f;
        float e1 = (col + 1 <= qg0) ? __expf(c1 * 0.125f + am1) : 0.f;
        float e2 = (col     <= qg1) ? __expf(c2 * 0.125f + am0) : 0.f;
        float e3 = (col + 1 <= qg1) ? __expf(c3 * 0.125f + am1) : 0.f;
        rsum0 += e0 + e1;
        rsum1 += e2 + e3;
        *(float2*)&Ps[ly * PSW + col]       = make_float2(e0, e1);
        *(float2*)&Ps[(ly + 8) * PSW + col] = make_float2(e2, e3);

        __syncthreads();   // all Kb reads done before refill / V reuse
    }

    // ---- V tile 0 prologue (K region now dead; latency hidden below) ----
    ld_vtile(Vp, 0, KV, t);
    asm volatile("cp.async.commit_group;\n" ::: "memory");

    // ---- row-sum reduction -> inv[r] ----
    rsum0 += __shfl_xor_sync(0xffffffffu, rsum0, 1);
    rsum0 += __shfl_xor_sync(0xffffffffu, rsum0, 2);
    rsum1 += __shfl_xor_sync(0xffffffffu, rsum1, 1);
    rsum1 += __shfl_xor_sync(0xffffffffu, rsum1, 2);
    if (lx == 0) {
        red[ly * 16 + w]       = rsum0;
        red[(ly + 8) * 16 + w] = rsum1;
    }
    __syncthreads();
    if (t < 256) {
        int r = t >> 4, x = t & 15;
        float s = red[r * 16 + x];
        s += __shfl_down_sync(0xffffffffu, s, 8, 16);
        s += __shfl_down_sync(0xffffffffu, s, 4, 16);
        s += __shfl_down_sync(0xffffffffu, s, 2, 16);
        s += __shfl_down_sync(0xffffffffu, s, 1, 16);
        if (x == 0) inv[r] = 1.0f / s;
    }
    __syncthreads();

    // ---- write normalized P (zeros beyond causal reach) ----
    {
        int r = t >> 5, x = t & 31;
        float invr = inv[r];
        float* orow = attw + ((bh * SS_) + q0 + r) * (size_t)SS_;
        const int JMAX = num_kt * TKEY;
#pragma unroll 4
        for (int it = 0; it < 16; it++) {
            int col = it * 128 + x * 4;
            float4 v;
            if (col < JMAX) {
                float4 p = *(const float4*)&Ps[r * PSW + col];
                v = make_float4(p.x * invr, p.y * invr, p.z * invr, p.w * invr);
            } else {
                v = make_float4(0.f, 0.f, 0.f, 0.f);
            }
            *(float4*)&orow[col] = v;
        }
    }

    // =================== PV phase (split-TF32 mma) ===================
    {
        float acc[8][4];
#pragma unroll
        for (int nf = 0; nf < 8; nf++)
#pragma unroll
            for (int i = 0; i < 4; i++) acc[nf][i] = 0.f;

        for (int kt2 = 0; kt2 < num_kt; kt2++) {
            if (kt2 + 1 < num_kt) {
                ld_vtile(Vp, (kt2 + 1) * TKEY, KV + ((kt2 + 1) & 1) * VTILE, t);
                asm volatile("cp.async.commit_group;\n" ::: "memory");
                asm volatile("cp.async.wait_group 1;\n" ::: "memory");
            } else {
                asm volatile("cp.async.wait_group 0;\n" ::: "memory");
            }
            __syncthreads();

            const float* Vb = KV + (kt2 & 1) * VTILE;
            const int j0w = kt2 * TKEY + w * 8;

            // A-frag: P[16 x 8keys] (warp's keys), conflict-free LDS
            float p0 = Ps[ly * PSW + j0w + lx];
            float p1 = Ps[(ly + 8) * PSW + j0w + lx];
            float p2 = Ps[ly * PSW + j0w + lx + 4];
            float p3 = Ps[(ly + 8) * PSW + j0w + lx + 4];
            uint32_t ph0 = f2tf(p0), pl0 = f2tf(p0 - __uint_as_float(ph0));
            uint32_t ph1 = f2tf(p1), pl1 = f2tf(p1 - __uint_as_float(ph1));
            uint32_t ph2 = f2tf(p2), pl2 = f2tf(p2 - __uint_as_float(ph2));
            uint32_t ph3 = f2tf(p3), pl3 = f2tf(p3 - __uint_as_float(ph3));

#pragma unroll
            for (int nf = 0; nf < 8; nf++) {
                // B-frag: B[n][k] = V[key][d] -> V[(w8+lx(+4))][nf*8+ly]
                float b0f = Vb[(w * 8 + lx) * VPAD + nf * 8 + ly];
                float b1f = Vb[(w * 8 + lx + 4) * VPAD + nf * 8 + ly];
                uint32_t vh0 = f2tf(b0f), vl0 = f2tf(b0f - __uint_as_float(vh0));
                uint32_t vh1 = f2tf(b1f), vl1 = f2tf(b1f - __uint_as_float(vh1));
                MMA_TF32(acc[nf][0], acc[nf][1], acc[nf][2], acc[nf][3],
                         ph0, ph1, ph2, ph3, vh0, vh1);
                MMA_TF32(acc[nf][0], acc[nf][1], acc[nf][2], acc[nf][3],
                         ph0, ph1, ph2, ph3, vl0, vl1);
                MMA_TF32(acc[nf][0], acc[nf][1], acc[nf][2], acc[nf][3],
                         pl0, pl1, pl2, pl3, vh0, vh1);
            }
            __syncthreads();   // all Vb reads done before refill / rb reuse
        }

        // ---- cross-warp reduce: 16 partial O[16][64] -> g_att ----
        float* rb = KV;   // 16 x (16 x 68) = 17408 floats <= KVREG
#pragma unroll
        for (int nf = 0; nf < 8; nf++) {
            *(float2*)&rb[w * 1088 + ly * 68 + nf * 8 + 2 * lx] =
                make_float2(acc[nf][0], acc[nf][1]);
            *(float2*)&rb[w * 1088 + (ly + 8) * 68 + nf * 8 + 2 * lx] =
                make_float2(acc[nf][2], acc[nf][3]);
        }
        __syncthreads();
        {
            int r = t >> 5, c = (t & 31) * 2;
            float invr = inv[r];
            float2 s = make_float2(0.f, 0.f);
#pragma unroll
            for (int w2 = 0; w2 < 16; w2++) {
                float2 x2 = *(const float2*)&rb[w2 * 1088 + r * 68 + c];
                s.x += x2.x; s.y += x2.y;
            }
            s.x *= invr; s.y *= invr;
            *(float2*)&g_att[((size_t)(b * SS_) + q0 + r) * DD_ + h * 64 + c] = s;
        }
    }
}

// ============================================================================
extern "C" void kernel_launch(void* const* d_in, const int* in_sizes, int n_in,
                              void* d_out, int out_size)
{
    (void)in_sizes; (void)n_in; (void)out_size;
    const float* x     = (const float*)d_in[0];
    const float* amask = (const float*)d_in[1];
    const float* W_in  = (const float*)d_in[2];
    const float* b_in  = (const float*)d_in[3];
    const float* W_out = (const float*)d_in[4];
    const float* b_out = (const float*)d_in[5];

    float* out  = (float*)d_out;
    float* attw = out + (size_t)BB_ * SS_ * DD_;   // tuple order: (out, attn_weights)

    cudaFuncSetAttribute(attn_kernel, cudaFuncAttributeMaxDynamicSharedMemorySize,
                         ATTN_SMEM_BYTES);
    cudaFuncSetAttribute(mma_gemm, cudaFuncAttributeMaxDynamicSharedMemorySize,
                         GSMEM_BYTES);

    // 0) transpose weights into K-major [N,K] scratch
    transpose_kernel<<<dim3(96, 32), dim3(32, 8)>>>(W_in, 3072, 0);
    transpose_kernel<<<dim3(32, 32), dim3(32, 8)>>>(W_out, 1024, 3072 * 1024);

    // 1) QKV projection (TF32 mma.sync) -> g_q/g_k/g_v
    mma_gemm<<<dim3(24, 64), 256, GSMEM_BYTES>>>(x, 0, b_in, nullptr, 3072, 0);

    // 2) attention (split-TF32 mma scores + split-TF32 mma PV)
    attn_kernel<<<dim3(SS_ / 16, HH_, BB_), 512, ATTN_SMEM_BYTES>>>(amask, attw);

    // 3) output projection (TF32 mma.sync) -> d_out head
    mma_gemm<<<dim3(8, 64), 256, GSMEM_BYTES>>>(nullptr, 3072 * 1024, b_out, out, 1024, 1);
}

// round 15
// speedup vs baseline: 1.6236x; 1.1309x over previous
#include <cuda_runtime.h>
#include <cuda_bf16.h>
#include <math.h>
#include <stdint.h>

#define BB_ 4
#define SS_ 2048
#define DD_ 1024
#define HH_ 16
#define DH_ 64
#define NQKV ((size_t)BB_ * HH_ * SS_ * DH_)

// ---------------- scratch (device globals: allocation-free) ----------------
__device__ float g_att[(size_t)BB_ * SS_ * DD_];            // merged-head attn out
__device__ float g_wt[(size_t)3072 * 1024 + 1024 * 1024];   // W_in^T, W_out^T
// bf16 hi/lo split operands (written by projection epilogue)
__device__ __align__(16) __nv_bfloat16 g_qh[NQKV], g_ql[NQKV];   // [bh][s][d]
__device__ __align__(16) __nv_bfloat16 g_kh[NQKV], g_kl[NQKV];   // [bh][s][d]
__device__ __align__(16) __nv_bfloat16 g_vh[NQKV], g_vl[NQKV];   // [bh][d][s] (transposed)

// =============================== PTX helpers ===============================
__device__ __forceinline__ uint32_t smem_u32(const void* p) {
    uint32_t a;
    asm("{ .reg .u64 t; cvta.to.shared.u64 t, %1; cvt.u32.u64 %0, t; }"
        : "=r"(a) : "l"(p));
    return a;
}

__device__ __forceinline__ uint32_t f2tf(float x) {
    uint32_t r;
    asm("cvt.rna.tf32.f32 %0, %1;" : "=r"(r) : "f"(x));
    return r;
}

// pack two floats into bf16x2: low half = x0, high half = x1
__device__ __forceinline__ uint32_t pack2bf(float x0, float x1) {
    uint32_t r;
    asm("cvt.rn.bf16x2.f32 %0, %1, %2;" : "=r"(r) : "f"(x1), "f"(x0));
    return r;
}
// hi/lo split of a float pair into packed bf16x2
__device__ __forceinline__ void split2(float x0, float x1, uint32_t& ph, uint32_t& pl) {
    ph = pack2bf(x0, x1);
    float h0 = __uint_as_float(ph << 16);
    float h1 = __uint_as_float(ph & 0xffff0000u);
    pl = pack2bf(x0 - h0, x1 - h1);
}

#define MMA_TF32(c0,c1,c2,c3, a0,a1,a2,a3, b0,b1) \
    asm volatile( \
        "mma.sync.aligned.m16n8k8.row.col.f32.tf32.tf32.f32 " \
        "{%0,%1,%2,%3}, {%4,%5,%6,%7}, {%8,%9}, {%0,%1,%2,%3};" \
        : "+f"(c0), "+f"(c1), "+f"(c2), "+f"(c3) \
        : "r"(a0), "r"(a1), "r"(a2), "r"(a3), "r"(b0), "r"(b1))

#define MMA_BF16(c0,c1,c2,c3, a0,a1,a2,a3, b0,b1) \
    asm volatile( \
        "mma.sync.aligned.m16n8k16.row.col.f32.bf16.bf16.f32 " \
        "{%0,%1,%2,%3}, {%4,%5,%6,%7}, {%8,%9}, {%0,%1,%2,%3};" \
        : "+f"(c0), "+f"(c1), "+f"(c2), "+f"(c3) \
        : "r"(a0), "r"(a1), "r"(a2), "r"(a3), "r"(b0), "r"(b1))

// ============================================================================
// W transpose: Wt[n*1024 + k] = W[k*N + n]
// ============================================================================
__global__ void transpose_kernel(const float* __restrict__ W, int N, int out_off)
{
    __shared__ float tile[32][33];
    int n0 = blockIdx.x * 32, k0 = blockIdx.y * 32;
    int tx = threadIdx.x, ty = threadIdx.y;   // 32 x 8
#pragma unroll
    for (int i = 0; i < 32; i += 8)
        tile[ty + i][tx] = W[(size_t)(k0 + ty + i) * N + n0 + tx];
    __syncthreads();
    float* Wt = g_wt + out_off;
#pragma unroll
    for (int i = 0; i < 32; i += 8)
        Wt[(size_t)(n0 + ty + i) * 1024 + k0 + tx] = tile[tx][ty + i];
}

// ============================================================================
// TF32 mma.sync GEMM: C[M,N] = A[M,1024] @ W[1024,N] + b
// mode 0: epilogue writes bf16 hi/lo Q/K (row layout) and V (transposed)
// mode 1: A := g_att, dense fp32 out
// ============================================================================
#define ASTR 36
#define TILEF (128 * ASTR)
#define GSTAGES 3
#define GSMEM_BYTES (GSTAGES * 2 * TILEF * 4)   // 110,592

__device__ __forceinline__ void ld_tile(const float* __restrict__ src, int row0,
                                        int k0, float* dst, int t)
{
#pragma unroll
    for (int i = 0; i < 4; i++) {
        int idx = t + i * 256;
        int r = idx >> 3, c = idx & 7;
        const float* g = src + (size_t)(row0 + r) * 1024 + k0 + c * 4;
        uint32_t d = smem_u32(dst + r * ASTR + c * 4);
        asm volatile("cp.async.cg.shared.global [%0], [%1], 16;\n"
                     :: "r"(d), "l"(g));
    }
}

__global__ __launch_bounds__(256)
void mma_gemm(const float* __restrict__ A_, int wt_off,
              const float* __restrict__ bias, float* __restrict__ Cout,
              int Ntot, int mode)
{
    extern __shared__ __align__(16) float sm[];
    const float* A  = (mode == 1) ? g_att : A_;
    const float* Bt = g_wt + wt_off;
    float* As = sm;
    float* Bs = sm + GSTAGES * TILEF;

    const int t = threadIdx.x, wid = t >> 5, lane = t & 31;
    const int n0 = blockIdx.x * 128, m0 = blockIdx.y * 128;
    const int wm0 = (wid >> 2) * 64, wn0 = (wid & 3) * 32;
    const int ly = lane >> 2, lx = lane & 3;

    float c[4][4][4];
#pragma unroll
    for (int mf = 0; mf < 4; mf++)
#pragma unroll
        for (int nf = 0; nf < 4; nf++)
#pragma unroll
            for (int i = 0; i < 4; i++) c[mf][nf][i] = 0.f;

#pragma unroll
    for (int j = 0; j < 2; j++) {
        ld_tile(A,  m0, j * 32, As + j * TILEF, t);
        ld_tile(Bt, n0, j * 32, Bs + j * TILEF, t);
        asm volatile("cp.async.commit_group;\n" ::: "memory");
    }

    for (int kt = 0; kt < 32; kt++) {
        asm volatile("cp.async.wait_group 1;\n" ::: "memory");
        __syncthreads();

        int j = kt + 2;
        if (j < 32) {
            int s = j - (j / 3) * 3;
            ld_tile(A,  m0, j * 32, As + s * TILEF, t);
            ld_tile(Bt, n0, j * 32, Bs + s * TILEF, t);
        }
        asm volatile("cp.async.commit_group;\n" ::: "memory");

        const int scur = kt - (kt / 3) * 3;
        const float* Asb = As + scur * TILEF;
        const float* Bsb = Bs + scur * TILEF;

#pragma unroll
        for (int ks = 0; ks < 4; ks++) {
            const int k0 = ks * 8;
            uint32_t af[4][4], bf[4][2];
#pragma unroll
            for (int mf = 0; mf < 4; mf++) {
                const float* ab = Asb + (wm0 + mf * 16 + ly) * ASTR + k0 + lx;
                af[mf][0] = f2tf(ab[0]);
                af[mf][1] = f2tf(ab[8 * ASTR]);
                af[mf][2] = f2tf(ab[4]);
                af[mf][3] = f2tf(ab[8 * ASTR + 4]);
            }
#pragma unroll
            for (int nf = 0; nf < 4; nf++) {
                const float* bb = Bsb + (wn0 + nf * 8 + ly) * ASTR + k0 + lx;
                bf[nf][0] = f2tf(bb[0]);
                bf[nf][1] = f2tf(bb[4]);
            }
#pragma unroll
            for (int mf = 0; mf < 4; mf++)
#pragma unroll
                for (int nf = 0; nf < 4; nf++)
                    MMA_TF32(c[mf][nf][0], c[mf][nf][1], c[mf][nf][2], c[mf][nf][3],
                             af[mf][0], af[mf][1], af[mf][2], af[mf][3],
                             bf[nf][0], bf[nf][1]);
        }
    }
    asm volatile("cp.async.wait_group 0;\n" ::: "memory");

#pragma unroll
    for (int mf = 0; mf < 4; mf++) {
        const int r0 = m0 + wm0 + mf * 16 + ly;
#pragma unroll
        for (int nf = 0; nf < 4; nf++) {
            const int cb = n0 + wn0 + nf * 8 + lx * 2;
            float2 bv = *(const float2*)&bias[cb];
            float2 v0 = make_float2(c[mf][nf][0] + bv.x, c[mf][nf][1] + bv.y);
            float2 v1 = make_float2(c[mf][nf][2] + bv.x, c[mf][nf][3] + bv.y);
            if (mode == 0) {
                const int sec = cb >> 10;
                const int h   = (cb & 1023) >> 6;
                const int dh0 = cb & 63;
                const int bb0 = r0 >> 11, ss0 = r0 & 2047;
                const int bb1 = (r0 + 8) >> 11, ss1 = (r0 + 8) & 2047;
                const size_t bhh0 = (size_t)(bb0 * HH_ + h);
                const size_t bhh1 = (size_t)(bb1 * HH_ + h);
                if (sec < 2) {
                    __nv_bfloat16* dh = (sec == 0) ? g_qh : g_kh;
                    __nv_bfloat16* dl = (sec == 0) ? g_ql : g_kl;
                    uint32_t ph, pl;
                    split2(v0.x, v0.y, ph, pl);
                    size_t i0 = (bhh0 * SS_ + ss0) * DH_ + dh0;
                    *(uint32_t*)&dh[i0] = ph;  *(uint32_t*)&dl[i0] = pl;
                    split2(v1.x, v1.y, ph, pl);
                    size_t i1 = (bhh1 * SS_ + ss1) * DH_ + dh0;
                    *(uint32_t*)&dh[i1] = ph;  *(uint32_t*)&dl[i1] = pl;
                } else {
                    // V transposed [d][key]
                    size_t vb0 = bhh0 * DH_, vb1 = bhh1 * DH_;
                    __nv_bfloat16 hx, hy;
                    hx = __float2bfloat16_rn(v0.x);
                    hy = __float2bfloat16_rn(v0.y);
                    g_vh[(vb0 + dh0)     * SS_ + ss0] = hx;
                    g_vh[(vb0 + dh0 + 1) * SS_ + ss0] = hy;
                    g_vl[(vb0 + dh0)     * SS_ + ss0] = __float2bfloat16_rn(v0.x - __bfloat162float(hx));
                    g_vl[(vb0 + dh0 + 1) * SS_ + ss0] = __float2bfloat16_rn(v0.y - __bfloat162float(hy));
                    hx = __float2bfloat16_rn(v1.x);
                    hy = __float2bfloat16_rn(v1.y);
                    g_vh[(vb1 + dh0)     * SS_ + ss1] = hx;
                    g_vh[(vb1 + dh0 + 1) * SS_ + ss1] = hy;
                    g_vl[(vb1 + dh0)     * SS_ + ss1] = __float2bfloat16_rn(v1.x - __bfloat162float(hx));
                    g_vl[(vb1 + dh0 + 1) * SS_ + ss1] = __float2bfloat16_rn(v1.y - __bfloat162float(hy));
                }
            } else {
                *(float2*)&Cout[(size_t)r0 * Ntot + cb] = v0;
                *(float2*)&Cout[(size_t)(r0 + 8) * Ntot + cb] = v1;
            }
        }
    }
}

// ============================================================================
// Fused attention, 512 threads (16 warps) per block = (b, h, 16-query tile).
//   Scores: bf16-pair m16n8k16 mma (3 terms), operands precomputed hi/lo.
//   PV:     bf16-pair m16n8k16 mma, V pre-transposed; P split on the fly.
// ============================================================================
#define TKEY 128
#define PSW 2052
#define KSTR 72                       // K tile row stride (bf16)
#define KCOMP (128 * KSTR)            // 9216 bf16 per component
#define KSTAGE (2 * KCOMP)            // hi+lo per stage
#define VSTR 136                      // V^T tile row stride (bf16)
#define VCOMP (64 * VSTR)             // 8704 bf16
#define VSTAGE (2 * VCOMP)
#define QSTR 72
#define KVFLOATS 18432                // 2 K stages in floats (73,728 B)
// floats: Ps 32832 + KV 18432 + Qs 1152 + red 256 + inv 16
#define ATTN_SMEM_FLOATS (16*PSW + KVFLOATS + 1152 + 256 + 16)
#define ATTN_SMEM_BYTES  (ATTN_SMEM_FLOATS * 4)   // 210,752

// K tile: [comp][128 keys][64 d] bf16, 16B chunks, 512 thr x 4
__device__ __forceinline__ void ld_ktile2(const __nv_bfloat16* __restrict__ kh,
                                          const __nv_bfloat16* __restrict__ kl,
                                          int row0, __nv_bfloat16* dst, int t)
{
#pragma unroll
    for (int i = 0; i < 4; i++) {
        int idx = t + i * 512;
        int comp = idx >> 10, rem = idx & 1023;
        int r = rem >> 3, c = rem & 7;
        const __nv_bfloat16* g = (comp ? kl : kh) + (size_t)(row0 + r) * DH_ + c * 8;
        uint32_t d = smem_u32(dst + comp * KCOMP + r * KSTR + c * 8);
        asm volatile("cp.async.cg.shared.global [%0], [%1], 16;\n"
                     :: "r"(d), "l"(g));
    }
}

// V tile: [comp][64 d][128 keys] bf16
__device__ __forceinline__ void ld_vtile2(const __nv_bfloat16* __restrict__ vh,
                                          const __nv_bfloat16* __restrict__ vl,
                                          int row0, __nv_bfloat16* dst, int t)
{
#pragma unroll
    for (int i = 0; i < 4; i++) {
        int idx = t + i * 512;
        int comp = idx >> 10, rem = idx & 1023;
        int d = rem >> 4, c = rem & 15;
        const __nv_bfloat16* g = (comp ? vl : vh) + (size_t)d * SS_ + row0 + c * 8;
        uint32_t dd = smem_u32(dst + comp * VCOMP + d * VSTR + c * 8);
        asm volatile("cp.async.cg.shared.global [%0], [%1], 16;\n"
                     :: "r"(dd), "l"(g));
    }
}

__global__ __launch_bounds__(512, 1)
void attn_kernel(const float* __restrict__ amask, float* __restrict__ attw)
{
    extern __shared__ __align__(16) float sm[];
    float* Ps   = sm;                               // 16 x PSW fp32
    float* KVf  = sm + 16 * PSW;                    // K/V tiles + reduce buf
    __nv_bfloat16* KVbf = (__nv_bfloat16*)KVf;
    __nv_bfloat16* Qsbf = (__nv_bfloat16*)(KVf + KVFLOATS);   // 2 x 16 x QSTR
    float* red = KVf + KVFLOATS + 1152 / 2 * 1 + 576;          // (see note below)
    // note: Qs occupies 2304 bf16 = 1152 floats -> red starts at +1152 floats
    red = KVf + KVFLOATS + 1152;
    float* inv = red + 256;

    const int t  = threadIdx.x;
    const int qt = blockIdx.x, h = blockIdx.y, b = blockIdx.z;
    const int q0 = qt * 16;
    const size_t bh = (size_t)(b * HH_ + h);
    const __nv_bfloat16* Qh = g_qh + bh * SS_ * DH_;
    const __nv_bfloat16* Ql = g_ql + bh * SS_ * DH_;
    const __nv_bfloat16* Kh = g_kh + bh * SS_ * DH_;
    const __nv_bfloat16* Kl = g_kl + bh * SS_ * DH_;
    const __nv_bfloat16* Vh = g_vh + bh * DH_ * SS_;
    const __nv_bfloat16* Vl = g_vl + bh * DH_ * SS_;

    const int w = t >> 5, lane = t & 31;
    const int ly = lane >> 2, lx = lane & 3;

    // ---- load Q tile [2 comp][16][64] bf16 ----
    if (t < 256) {
        int comp = t >> 7, rem = t & 127, r = rem >> 3, c = rem & 7;
        const __nv_bfloat16* g = (comp ? Ql : Qh) + (size_t)(q0 + r) * DH_ + c * 8;
        *(uint4*)&Qsbf[comp * 16 * QSTR + r * QSTR + c * 8] = *(const uint4*)g;
    }

    const int num_kt = q0 / TKEY + 1;

    // ---- prologue: K tile 0 ----
    ld_ktile2(Kh, Kl, 0, KVbf, t);
    asm volatile("cp.async.commit_group;\n" ::: "memory");
    __syncthreads();   // Qs visible

    // ---- hoist Q a-fragments (packed bf16x2) ----
    uint32_t qah[4][4], qal[4][4];
    {
        const __nv_bfloat16* Qsh = Qsbf;
        const __nv_bfloat16* Qsl = Qsbf + 16 * QSTR;
#pragma unroll
        for (int ks = 0; ks < 4; ks++) {
            int o = ks * 16 + 2 * lx;
            qah[ks][0] = *(const uint32_t*)&Qsh[ly * QSTR + o];
            qah[ks][1] = *(const uint32_t*)&Qsh[(ly + 8) * QSTR + o];
            qah[ks][2] = *(const uint32_t*)&Qsh[ly * QSTR + o + 8];
            qah[ks][3] = *(const uint32_t*)&Qsh[(ly + 8) * QSTR + o + 8];
            qal[ks][0] = *(const uint32_t*)&Qsl[ly * QSTR + o];
            qal[ks][1] = *(const uint32_t*)&Qsl[(ly + 8) * QSTR + o];
            qal[ks][2] = *(const uint32_t*)&Qsl[ly * QSTR + o + 8];
            qal[ks][3] = *(const uint32_t*)&Qsl[(ly + 8) * QSTR + o + 8];
        }
    }

    float rsum0 = 0.f, rsum1 = 0.f;

    // =================== score phase ===================
    for (int kt = 0; kt < num_kt; kt++) {
        const int j0 = kt * TKEY;
        if (kt + 1 < num_kt) {
            ld_ktile2(Kh, Kl, j0 + TKEY, KVbf + ((kt + 1) & 1) * KSTAGE, t);
            asm volatile("cp.async.commit_group;\n" ::: "memory");
            asm volatile("cp.async.wait_group 1;\n" ::: "memory");
        } else {
            asm volatile("cp.async.wait_group 0;\n" ::: "memory");
        }
        __syncthreads();

        const __nv_bfloat16* Kbh = KVbf + (kt & 1) * KSTAGE;
        const __nv_bfloat16* Kbl = Kbh + KCOMP;
        float c0 = 0.f, c1 = 0.f, c2 = 0.f, c3 = 0.f;
        const int krow = (w * 8 + ly) * KSTR;

#pragma unroll
        for (int ks = 0; ks < 4; ks++) {
            int o = ks * 16 + 2 * lx;
            uint32_t bh0 = *(const uint32_t*)&Kbh[krow + o];
            uint32_t bh1 = *(const uint32_t*)&Kbh[krow + o + 8];
            uint32_t bl0 = *(const uint32_t*)&Kbl[krow + o];
            uint32_t bl1 = *(const uint32_t*)&Kbl[krow + o + 8];
            MMA_BF16(c0, c1, c2, c3, qah[ks][0], qah[ks][1], qah[ks][2], qah[ks][3], bh0, bh1);
            MMA_BF16(c0, c1, c2, c3, qah[ks][0], qah[ks][1], qah[ks][2], qah[ks][3], bl0, bl1);
            MMA_BF16(c0, c1, c2, c3, qal[ks][0], qal[ks][1], qal[ks][2], qal[ks][3], bh0, bh1);
        }

        const int col = j0 + w * 8 + 2 * lx;
        const float am0 = amask[b * SS_ + col];
        const float am1 = amask[b * SS_ + col + 1];
        const int qg0 = q0 + ly, qg1 = q0 + ly + 8;
        float e0 = (col     <= qg0) ? __expf(c0 * 0.125f + am0) : 0.f;
        float e1 = (col + 1 <= qg0) ? __expf(c1 * 0.125f + am1) : 0.f;
        float e2 = (col     <= qg1) ? __expf(c2 * 0.125f + am0) : 0.f;
        float e3 = (col + 1 <= qg1) ? __expf(c3 * 0.125f + am1) : 0.f;
        rsum0 += e0 + e1;
        rsum1 += e2 + e3;
        *(float2*)&Ps[ly * PSW + col]       = make_float2(e0, e1);
        *(float2*)&Ps[(ly + 8) * PSW + col] = make_float2(e2, e3);

        __syncthreads();
    }

    // ---- V tile 0 prologue (K region dead; latency hidden below) ----
    ld_vtile2(Vh, Vl, 0, KVbf, t);
    asm volatile("cp.async.commit_group;\n" ::: "memory");

    // ---- row-sum reduction -> inv[r] ----
    rsum0 += __shfl_xor_sync(0xffffffffu, rsum0, 1);
    rsum0 += __shfl_xor_sync(0xffffffffu, rsum0, 2);
    rsum1 += __shfl_xor_sync(0xffffffffu, rsum1, 1);
    rsum1 += __shfl_xor_sync(0xffffffffu, rsum1, 2);
    if (lx == 0) {
        red[ly * 16 + w]       = rsum0;
        red[(ly + 8) * 16 + w] = rsum1;
    }
    __syncthreads();
    if (t < 256) {
        int r = t >> 4, x = t & 15;
        float s = red[r * 16 + x];
        s += __shfl_down_sync(0xffffffffu, s, 8, 16);
        s += __shfl_down_sync(0xffffffffu, s, 4, 16);
        s += __shfl_down_sync(0xffffffffu, s, 2, 16);
        s += __shfl_down_sync(0xffffffffu, s, 1, 16);
        if (x == 0) inv[r] = 1.0f / s;
    }
    __syncthreads();

    // ---- write normalized P ----
    {
        int r = t >> 5, x = t & 31;
        float invr = inv[r];
        float* orow = attw + ((bh * SS_) + q0 + r) * (size_t)SS_;
        const int JMAX = num_kt * TKEY;
#pragma unroll 4
        for (int it = 0; it < 16; it++) {
            int col = it * 128 + x * 4;
            float4 v;
            if (col < JMAX) {
                float4 p = *(const float4*)&Ps[r * PSW + col];
                v = make_float4(p.x * invr, p.y * invr, p.z * invr, p.w * invr);
            } else {
                v = make_float4(0.f, 0.f, 0.f, 0.f);
            }
            *(float4*)&orow[col] = v;
        }
    }

    // =================== PV phase (bf16-pair mma) ===================
    {
        const int s8 = w & 7;              // 16-key slab within tile
        const int dhalf = (w >> 3) * 32;   // d-half
        float acc[4][4];
#pragma unroll
        for (int nf = 0; nf < 4; nf++)
#pragma unroll
            for (int i = 0; i < 4; i++) acc[nf][i] = 0.f;

        for (int kt2 = 0; kt2 < num_kt; kt2++) {
            if (kt2 + 1 < num_kt) {
                ld_vtile2(Vh, Vl, (kt2 + 1) * TKEY, KVbf + ((kt2 + 1) & 1) * VSTAGE, t);
                asm volatile("cp.async.commit_group;\n" ::: "memory");
                asm volatile("cp.async.wait_group 1;\n" ::: "memory");
            } else {
                asm volatile("cp.async.wait_group 0;\n" ::: "memory");
            }
            __syncthreads();

            const __nv_bfloat16* Vbh = KVbf + (kt2 & 1) * VSTAGE;
            const __nv_bfloat16* Vbl = Vbh + VCOMP;
            const int j0w = kt2 * TKEY + s8 * 16;

            // ---- A-frag: P rows (ly, ly+8), keys j0w+2lx(+1), +8(+9) ----
            float2 p0 = *(const float2*)&Ps[ly * PSW + j0w + 2 * lx];
            float2 p1 = *(const float2*)&Ps[(ly + 8) * PSW + j0w + 2 * lx];
            float2 p2 = *(const float2*)&Ps[ly * PSW + j0w + 2 * lx + 8];
            float2 p3 = *(const float2*)&Ps[(ly + 8) * PSW + j0w + 2 * lx + 8];
            uint32_t pah[4], pal[4];
            split2(p0.x, p0.y, pah[0], pal[0]);
            split2(p1.x, p1.y, pah[1], pal[1]);
            split2(p2.x, p2.y, pah[2], pal[2]);
            split2(p3.x, p3.y, pah[3], pal[3]);

#pragma unroll
            for (int nf = 0; nf < 4; nf++) {
                const int drow = (dhalf + nf * 8 + ly) * VSTR + s8 * 16 + 2 * lx;
                uint32_t vh0 = *(const uint32_t*)&Vbh[drow];
                uint32_t vh1 = *(const uint32_t*)&Vbh[drow + 8];
                uint32_t vl0 = *(const uint32_t*)&Vbl[drow];
                uint32_t vl1 = *(const uint32_t*)&Vbl[drow + 8];
                MMA_BF16(acc[nf][0], acc[nf][1], acc[nf][2], acc[nf][3],
                         pah[0], pah[1], pah[2], pah[3], vh0, vh1);
                MMA_BF16(acc[nf][0], acc[nf][1], acc[nf][2], acc[nf][3],
                         pah[0], pah[1], pah[2], pah[3], vl0, vl1);
                MMA_BF16(acc[nf][0], acc[nf][1], acc[nf][2], acc[nf][3],
                         pal[0], pal[1], pal[2], pal[3], vh0, vh1);
            }
            __syncthreads();
        }

        // ---- cross-warp reduce (8 partials per d-half) -> g_att ----
        float* rb = KVf;   // 16 warps x 16 rows x 34 = 8704 floats
#pragma unroll
        for (int nf = 0; nf < 4; nf++) {
            *(float2*)&rb[w * 544 + ly * 34 + nf * 8 + 2 * lx] =
                make_float2(acc[nf][0], acc[nf][1]);
            *(float2*)&rb[w * 544 + (ly + 8) * 34 + nf * 8 + 2 * lx] =
                make_float2(acc[nf][2], acc[nf][3]);
        }
        __syncthreads();
        {
            int r = t >> 5, c2 = (t & 31) * 2;
            int dh = c2 >> 5, loc = c2 & 31;
            float invr = inv[r];
            float2 s = make_float2(0.f, 0.f);
#pragma unroll
            for (int w2 = 0; w2 < 8; w2++) {
                float2 x2 = *(const float2*)&rb[(dh * 8 + w2) * 544 + r * 34 + loc];
                s.x += x2.x; s.y += x2.y;
            }
            s.x *= invr; s.y *= invr;
            *(float2*)&g_att[((size_t)(b * SS_) + q0 + r) * DD_ + h * 64 + c2] = s;
        }
    }
}

// ============================================================================
extern "C" void kernel_launch(void* const* d_in, const int* in_sizes, int n_in,
                              void* d_out, int out_size)
{
    (void)in_sizes; (void)n_in; (void)out_size;
    const float* x     = (const float*)d_in[0];
    const float* amask = (const float*)d_in[1];
    const float* W_in  = (const float*)d_in[2];
    const float* b_in  = (const float*)d_in[3];
    const float* W_out = (const float*)d_in[4];
    const float* b_out = (const float*)d_in[5];

    float* out  = (float*)d_out;
    float* attw = out + (size_t)BB_ * SS_ * DD_;   // tuple order: (out, attn_weights)

    cudaFuncSetAttribute(attn_kernel, cudaFuncAttributeMaxDynamicSharedMemorySize,
                         ATTN_SMEM_BYTES);
    cudaFuncSetAttribute(mma_gemm, cudaFuncAttributeMaxDynamicSharedMemorySize,
                         GSMEM_BYTES);

    // 0) transpose weights into K-major [N,K] scratch
    transpose_kernel<<<dim3(96, 32), dim3(32, 8)>>>(W_in, 3072, 0);
    transpose_kernel<<<dim3(32, 32), dim3(32, 8)>>>(W_out, 1024, 3072 * 1024);

    // 1) QKV projection -> bf16 hi/lo Q/K/V (V transposed)
    mma_gemm<<<dim3(24, 64), 256, GSMEM_BYTES>>>(x, 0, b_in, nullptr, 3072, 0);

    // 2) attention (bf16-pair mma scores + PV)
    attn_kernel<<<dim3(SS_ / 16, HH_, BB_), 512, ATTN_SMEM_BYTES>>>(amask, attw);

    // 3) output projection -> d_out head
    mma_gemm<<<dim3(8, 64), 256, GSMEM_BYTES>>>(nullptr, 3072 * 1024, b_out, out, 1024, 1);
}

// round 16
// speedup vs baseline: 1.8267x; 1.1251x over previous
#include <cuda_runtime.h>
#include <cuda_bf16.h>
#include <math.h>
#include <stdint.h>

#define BB_ 4
#define SS_ 2048
#define DD_ 1024
#define HH_ 16
#define DH_ 64
#define NQKV ((size_t)BB_ * HH_ * SS_ * DH_)

// ---------------- scratch (device globals: allocation-free) ----------------
__device__ float g_att[(size_t)BB_ * SS_ * DD_];            // merged-head attn out
__device__ float g_wt[(size_t)3072 * 1024 + 1024 * 1024];   // W_in^T, W_out^T
// bf16 hi/lo split operands (written by projection epilogue)
__device__ __align__(16) __nv_bfloat16 g_qh[NQKV], g_ql[NQKV];   // [bh][s][d]
__device__ __align__(16) __nv_bfloat16 g_kh[NQKV], g_kl[NQKV];   // [bh][s][d]
__device__ __align__(16) __nv_bfloat16 g_vh[NQKV], g_vl[NQKV];   // [bh][d][s] (transposed)

// =============================== PTX helpers ===============================
__device__ __forceinline__ uint32_t smem_u32(const void* p) {
    uint32_t a;
    asm("{ .reg .u64 t; cvta.to.shared.u64 t, %1; cvt.u32.u64 %0, t; }"
        : "=r"(a) : "l"(p));
    return a;
}

__device__ __forceinline__ uint32_t f2tf(float x) {
    uint32_t r;
    asm("cvt.rna.tf32.f32 %0, %1;" : "=r"(r) : "f"(x));
    return r;
}

// pack two floats into bf16x2: low half = x0, high half = x1
__device__ __forceinline__ uint32_t pack2bf(float x0, float x1) {
    uint32_t r;
    asm("cvt.rn.bf16x2.f32 %0, %1, %2;" : "=r"(r) : "f"(x1), "f"(x0));
    return r;
}
// hi/lo split of a float pair into packed bf16x2
__device__ __forceinline__ void split2(float x0, float x1, uint32_t& ph, uint32_t& pl) {
    ph = pack2bf(x0, x1);
    float h0 = __uint_as_float(ph << 16);
    float h1 = __uint_as_float(ph & 0xffff0000u);
    pl = pack2bf(x0 - h0, x1 - h1);
}

#define MMA_TF32(c0,c1,c2,c3, a0,a1,a2,a3, b0,b1) \
    asm volatile( \
        "mma.sync.aligned.m16n8k8.row.col.f32.tf32.tf32.f32 " \
        "{%0,%1,%2,%3}, {%4,%5,%6,%7}, {%8,%9}, {%0,%1,%2,%3};" \
        : "+f"(c0), "+f"(c1), "+f"(c2), "+f"(c3) \
        : "r"(a0), "r"(a1), "r"(a2), "r"(a3), "r"(b0), "r"(b1))

#define MMA_BF16(c0,c1,c2,c3, a0,a1,a2,a3, b0,b1) \
    asm volatile( \
        "mma.sync.aligned.m16n8k16.row.col.f32.bf16.bf16.f32 " \
        "{%0,%1,%2,%3}, {%4,%5,%6,%7}, {%8,%9}, {%0,%1,%2,%3};" \
        : "+f"(c0), "+f"(c1), "+f"(c2), "+f"(c3) \
        : "r"(a0), "r"(a1), "r"(a2), "r"(a3), "r"(b0), "r"(b1))

// ============================================================================
// W transpose: Wt[n*1024 + k] = W[k*N + n]
// ============================================================================
__global__ void transpose_kernel(const float* __restrict__ W, int N, int out_off)
{
    __shared__ float tile[32][33];
    int n0 = blockIdx.x * 32, k0 = blockIdx.y * 32;
    int tx = threadIdx.x, ty = threadIdx.y;   // 32 x 8
#pragma unroll
    for (int i = 0; i < 32; i += 8)
        tile[ty + i][tx] = W[(size_t)(k0 + ty + i) * N + n0 + tx];
    __syncthreads();
    float* Wt = g_wt + out_off;
#pragma unroll
    for (int i = 0; i < 32; i += 8)
        Wt[(size_t)(n0 + ty + i) * 1024 + k0 + tx] = tile[tx][ty + i];
}

// ============================================================================
// TF32 mma.sync GEMM (unchanged): C[M,N] = A[M,1024] @ W[1024,N] + b
// mode 0: epilogue writes bf16 hi/lo Q/K (row layout) and V (transposed)
// mode 1: A := g_att, dense fp32 out
// ============================================================================
#define ASTR 36
#define TILEF (128 * ASTR)
#define GSTAGES 3
#define GSMEM_BYTES (GSTAGES * 2 * TILEF * 4)   // 110,592

__device__ __forceinline__ void ld_tile(const float* __restrict__ src, int row0,
                                        int k0, float* dst, int t)
{
#pragma unroll
    for (int i = 0; i < 4; i++) {
        int idx = t + i * 256;
        int r = idx >> 3, c = idx & 7;
        const float* g = src + (size_t)(row0 + r) * 1024 + k0 + c * 4;
        uint32_t d = smem_u32(dst + r * ASTR + c * 4);
        asm volatile("cp.async.cg.shared.global [%0], [%1], 16;\n"
                     :: "r"(d), "l"(g));
    }
}

__global__ __launch_bounds__(256)
void mma_gemm(const float* __restrict__ A_, int wt_off,
              const float* __restrict__ bias, float* __restrict__ Cout,
              int Ntot, int mode)
{
    extern __shared__ __align__(16) float sm[];
    const float* A  = (mode == 1) ? g_att : A_;
    const float* Bt = g_wt + wt_off;
    float* As = sm;
    float* Bs = sm + GSTAGES * TILEF;

    const int t = threadIdx.x, wid = t >> 5, lane = t & 31;
    const int n0 = blockIdx.x * 128, m0 = blockIdx.y * 128;
    const int wm0 = (wid >> 2) * 64, wn0 = (wid & 3) * 32;
    const int ly = lane >> 2, lx = lane & 3;

    float c[4][4][4];
#pragma unroll
    for (int mf = 0; mf < 4; mf++)
#pragma unroll
        for (int nf = 0; nf < 4; nf++)
#pragma unroll
            for (int i = 0; i < 4; i++) c[mf][nf][i] = 0.f;

#pragma unroll
    for (int j = 0; j < 2; j++) {
        ld_tile(A,  m0, j * 32, As + j * TILEF, t);
        ld_tile(Bt, n0, j * 32, Bs + j * TILEF, t);
        asm volatile("cp.async.commit_group;\n" ::: "memory");
    }

    for (int kt = 0; kt < 32; kt++) {
        asm volatile("cp.async.wait_group 1;\n" ::: "memory");
        __syncthreads();

        int j = kt + 2;
        if (j < 32) {
            int s = j - (j / 3) * 3;
            ld_tile(A,  m0, j * 32, As + s * TILEF, t);
            ld_tile(Bt, n0, j * 32, Bs + s * TILEF, t);
        }
        asm volatile("cp.async.commit_group;\n" ::: "memory");

        const int scur = kt - (kt / 3) * 3;
        const float* Asb = As + scur * TILEF;
        const float* Bsb = Bs + scur * TILEF;

#pragma unroll
        for (int ks = 0; ks < 4; ks++) {
            const int k0 = ks * 8;
            uint32_t af[4][4], bf[4][2];
#pragma unroll
            for (int mf = 0; mf < 4; mf++) {
                const float* ab = Asb + (wm0 + mf * 16 + ly) * ASTR + k0 + lx;
                af[mf][0] = f2tf(ab[0]);
                af[mf][1] = f2tf(ab[8 * ASTR]);
                af[mf][2] = f2tf(ab[4]);
                af[mf][3] = f2tf(ab[8 * ASTR + 4]);
            }
#pragma unroll
            for (int nf = 0; nf < 4; nf++) {
                const float* bb = Bsb + (wn0 + nf * 8 + ly) * ASTR + k0 + lx;
                bf[nf][0] = f2tf(bb[0]);
                bf[nf][1] = f2tf(bb[4]);
            }
#pragma unroll
            for (int mf = 0; mf < 4; mf++)
#pragma unroll
                for (int nf = 0; nf < 4; nf++)
                    MMA_TF32(c[mf][nf][0], c[mf][nf][1], c[mf][nf][2], c[mf][nf][3],
                             af[mf][0], af[mf][1], af[mf][2], af[mf][3],
                             bf[nf][0], bf[nf][1]);
        }
    }
    asm volatile("cp.async.wait_group 0;\n" ::: "memory");

#pragma unroll
    for (int mf = 0; mf < 4; mf++) {
        const int r0 = m0 + wm0 + mf * 16 + ly;
#pragma unroll
        for (int nf = 0; nf < 4; nf++) {
            const int cb = n0 + wn0 + nf * 8 + lx * 2;
            float2 bv = *(const float2*)&bias[cb];
            float2 v0 = make_float2(c[mf][nf][0] + bv.x, c[mf][nf][1] + bv.y);
            float2 v1 = make_float2(c[mf][nf][2] + bv.x, c[mf][nf][3] + bv.y);
            if (mode == 0) {
                const int sec = cb >> 10;
                const int h   = (cb & 1023) >> 6;
                const int dh0 = cb & 63;
                const int bb0 = r0 >> 11, ss0 = r0 & 2047;
                const int bb1 = (r0 + 8) >> 11, ss1 = (r0 + 8) & 2047;
                const size_t bhh0 = (size_t)(bb0 * HH_ + h);
                const size_t bhh1 = (size_t)(bb1 * HH_ + h);
                if (sec < 2) {
                    __nv_bfloat16* dh = (sec == 0) ? g_qh : g_kh;
                    __nv_bfloat16* dl = (sec == 0) ? g_ql : g_kl;
                    uint32_t ph, pl;
                    split2(v0.x, v0.y, ph, pl);
                    size_t i0 = (bhh0 * SS_ + ss0) * DH_ + dh0;
                    *(uint32_t*)&dh[i0] = ph;  *(uint32_t*)&dl[i0] = pl;
                    split2(v1.x, v1.y, ph, pl);
                    size_t i1 = (bhh1 * SS_ + ss1) * DH_ + dh0;
                    *(uint32_t*)&dh[i1] = ph;  *(uint32_t*)&dl[i1] = pl;
                } else {
                    // V transposed [d][key]
                    size_t vb0 = bhh0 * DH_, vb1 = bhh1 * DH_;
                    __nv_bfloat16 hx, hy;
                    hx = __float2bfloat16_rn(v0.x);
                    hy = __float2bfloat16_rn(v0.y);
                    g_vh[(vb0 + dh0)     * SS_ + ss0] = hx;
                    g_vh[(vb0 + dh0 + 1) * SS_ + ss0] = hy;
                    g_vl[(vb0 + dh0)     * SS_ + ss0] = __float2bfloat16_rn(v0.x - __bfloat162float(hx));
                    g_vl[(vb0 + dh0 + 1) * SS_ + ss0] = __float2bfloat16_rn(v0.y - __bfloat162float(hy));
                    hx = __float2bfloat16_rn(v1.x);
                    hy = __float2bfloat16_rn(v1.y);
                    g_vh[(vb1 + dh0)     * SS_ + ss1] = hx;
                    g_vh[(vb1 + dh0 + 1) * SS_ + ss1] = hy;
                    g_vl[(vb1 + dh0)     * SS_ + ss1] = __float2bfloat16_rn(v1.x - __bfloat162float(hx));
                    g_vl[(vb1 + dh0 + 1) * SS_ + ss1] = __float2bfloat16_rn(v1.y - __bfloat162float(hy));
                }
            } else {
                *(float2*)&Cout[(size_t)r0 * Ntot + cb] = v0;
                *(float2*)&Cout[(size_t)(r0 + 8) * Ntot + cb] = v1;
            }
        }
    }
}

// ============================================================================
// Fused attention, 512 threads (16 warps) per block = (b, h, 16-query tile).
//   WARP-PRIVATE K/V staging: each warp cp.asyncs only its own slice into a
//   private double buffer; NO block-wide syncs in the hot loops.
//   Scores: bf16-pair m16n8k16 mma (3 terms).
//   PV:     bf16-pair m16n8k16 mma, V pre-transposed.
// ============================================================================
#define TKEY 128
#define PSW 2052
#define QSTR 72
#define KVFLOATS 18432                 // 73,728 B shared staging region
// per-warp K slice: 8 keys x 72 bf16 x 2 comps = 1152 bf16/stage; 2 stages
#define KW_STAGE 1152
#define KW_STRIDE (2 * KW_STAGE)       // 2304 bf16 per warp
// per-warp V slice: 32 d x 16 keys x 2 comps = 1024 bf16/stage; 2 stages
#define VW_STAGE 1024
#define VW_STRIDE (2 * VW_STAGE)       // 2048 bf16 per warp
// floats: Ps 32832 + KV 18432 + Qs 1152 + red 256 + inv 16
#define ATTN_SMEM_FLOATS (16*PSW + KVFLOATS + 1152 + 256 + 16)
#define ATTN_SMEM_BYTES  (ATTN_SMEM_FLOATS * 4)   // 210,752

// Warp-private K slice: keys [key0, key0+8), 64 d, hi+lo. 128 chunks/4 per lane.
__device__ __forceinline__ void ld_kslice(const __nv_bfloat16* __restrict__ kh,
                                          const __nv_bfloat16* __restrict__ kl,
                                          int key0, __nv_bfloat16* dst, int lane)
{
#pragma unroll
    for (int i = 0; i < 4; i++) {
        int idx = lane + i * 32;
        int comp = idx >> 6, rem = idx & 63;
        int r = rem >> 3, c = rem & 7;
        const __nv_bfloat16* g = (comp ? kl : kh) + (size_t)(key0 + r) * DH_ + c * 8;
        uint32_t d = smem_u32(dst + comp * 576 + r * 72 + c * 8);
        asm volatile("cp.async.cg.shared.global [%0], [%1], 16;\n"
                     :: "r"(d), "l"(g));
    }
}

// Warp-private V slice: d [dhalf, dhalf+32), keys [key0, key0+16), hi+lo.
__device__ __forceinline__ void ld_vslice(const __nv_bfloat16* __restrict__ vh,
                                          const __nv_bfloat16* __restrict__ vl,
                                          int key0, int dhalf,
                                          __nv_bfloat16* dst, int lane)
{
#pragma unroll
    for (int i = 0; i < 4; i++) {
        int idx = lane + i * 32;
        int comp = idx >> 6, rem = idx & 63;
        int d = rem >> 1, c = rem & 1;
        const __nv_bfloat16* g = (comp ? vl : vh) + (size_t)(dhalf + d) * SS_ + key0 + c * 8;
        uint32_t dd = smem_u32(dst + comp * 512 + d * 16 + c * 8);
        asm volatile("cp.async.cg.shared.global [%0], [%1], 16;\n"
                     :: "r"(dd), "l"(g));
    }
}

__global__ __launch_bounds__(512, 1)
void attn_kernel(const float* __restrict__ amask, float* __restrict__ attw)
{
    extern __shared__ __align__(16) float sm[];
    float* Ps   = sm;                               // 16 x PSW fp32
    float* KVf  = sm + 16 * PSW;                    // warp-private staging
    __nv_bfloat16* KVbf = (__nv_bfloat16*)KVf;
    __nv_bfloat16* Qsbf = (__nv_bfloat16*)(KVf + KVFLOATS);   // 2 x 16 x QSTR
    float* red = KVf + KVFLOATS + 1152;
    float* inv = red + 256;

    const int t  = threadIdx.x;
    const int qt = blockIdx.x, h = blockIdx.y, b = blockIdx.z;
    const int q0 = qt * 16;
    const size_t bh = (size_t)(b * HH_ + h);
    const __nv_bfloat16* Qh = g_qh + bh * SS_ * DH_;
    const __nv_bfloat16* Ql = g_ql + bh * SS_ * DH_;
    const __nv_bfloat16* Kh = g_kh + bh * SS_ * DH_;
    const __nv_bfloat16* Kl = g_kl + bh * SS_ * DH_;
    const __nv_bfloat16* Vh = g_vh + bh * DH_ * SS_;
    const __nv_bfloat16* Vl = g_vl + bh * DH_ * SS_;

    const int w = t >> 5, lane = t & 31;
    const int ly = lane >> 2, lx = lane & 3;

    // ---- load Q tile [2 comp][16][64] bf16 ----
    if (t < 256) {
        int comp = t >> 7, rem = t & 127, r = rem >> 3, c = rem & 7;
        const __nv_bfloat16* g = (comp ? Ql : Qh) + (size_t)(q0 + r) * DH_ + c * 8;
        *(uint4*)&Qsbf[comp * 16 * QSTR + r * QSTR + c * 8] = *(const uint4*)g;
    }

    const int num_kt = q0 / TKEY + 1;
    __nv_bfloat16* Kw = KVbf + w * KW_STRIDE;

    // ---- prologue: warp-private K slice, tile 0 ----
    ld_kslice(Kh, Kl, w * 8, Kw, lane);
    asm volatile("cp.async.commit_group;\n" ::: "memory");
    __syncthreads();   // Qs visible to all warps

    // ---- hoist Q a-fragments (packed bf16x2) ----
    uint32_t qah[4][4], qal[4][4];
    {
        const __nv_bfloat16* Qsh = Qsbf;
        const __nv_bfloat16* Qsl = Qsbf + 16 * QSTR;
#pragma unroll
        for (int ks = 0; ks < 4; ks++) {
            int o = ks * 16 + 2 * lx;
            qah[ks][0] = *(const uint32_t*)&Qsh[ly * QSTR + o];
            qah[ks][1] = *(const uint32_t*)&Qsh[(ly + 8) * QSTR + o];
            qah[ks][2] = *(const uint32_t*)&Qsh[ly * QSTR + o + 8];
            qah[ks][3] = *(const uint32_t*)&Qsh[(ly + 8) * QSTR + o + 8];
            qal[ks][0] = *(const uint32_t*)&Qsl[ly * QSTR + o];
            qal[ks][1] = *(const uint32_t*)&Qsl[(ly + 8) * QSTR + o];
            qal[ks][2] = *(const uint32_t*)&Qsl[ly * QSTR + o + 8];
            qal[ks][3] = *(const uint32_t*)&Qsl[(ly + 8) * QSTR + o + 8];
        }
    }

    float rsum0 = 0.f, rsum1 = 0.f;

    // =================== score phase (no block syncs) ===================
    for (int kt = 0; kt < num_kt; kt++) {
        const int j0 = kt * TKEY;
        if (kt + 1 < num_kt) {
            ld_kslice(Kh, Kl, j0 + TKEY + w * 8, Kw + ((kt + 1) & 1) * KW_STAGE, lane);
            asm volatile("cp.async.commit_group;\n" ::: "memory");
            asm volatile("cp.async.wait_group 1;\n" ::: "memory");
        } else {
            asm volatile("cp.async.wait_group 0;\n" ::: "memory");
        }
        __syncwarp();

        const __nv_bfloat16* Kbh = Kw + (kt & 1) * KW_STAGE;
        const __nv_bfloat16* Kbl = Kbh + 576;
        float c0 = 0.f, c1 = 0.f, c2 = 0.f, c3 = 0.f;
        const int krow = ly * 72;

#pragma unroll
        for (int ks = 0; ks < 4; ks++) {
            int o = ks * 16 + 2 * lx;
            uint32_t bh0 = *(const uint32_t*)&Kbh[krow + o];
            uint32_t bh1 = *(const uint32_t*)&Kbh[krow + o + 8];
            uint32_t bl0 = *(const uint32_t*)&Kbl[krow + o];
            uint32_t bl1 = *(const uint32_t*)&Kbl[krow + o + 8];
            MMA_BF16(c0, c1, c2, c3, qah[ks][0], qah[ks][1], qah[ks][2], qah[ks][3], bh0, bh1);
            MMA_BF16(c0, c1, c2, c3, qah[ks][0], qah[ks][1], qah[ks][2], qah[ks][3], bl0, bl1);
            MMA_BF16(c0, c1, c2, c3, qal[ks][0], qal[ks][1], qal[ks][2], qal[ks][3], bh0, bh1);
        }

        const int col = j0 + w * 8 + 2 * lx;
        const float am0 = amask[b * SS_ + col];
        const float am1 = amask[b * SS_ + col + 1];
        const int qg0 = q0 + ly, qg1 = q0 + ly + 8;
        float e0 = (col     <= qg0) ? __expf(c0 * 0.125f + am0) : 0.f;
        float e1 = (col + 1 <= qg0) ? __expf(c1 * 0.125f + am1) : 0.f;
        float e2 = (col     <= qg1) ? __expf(c2 * 0.125f + am0) : 0.f;
        float e3 = (col + 1 <= qg1) ? __expf(c3 * 0.125f + am1) : 0.f;
        rsum0 += e0 + e1;
        rsum1 += e2 + e3;
        *(float2*)&Ps[ly * PSW + col]       = make_float2(e0, e1);
        *(float2*)&Ps[(ly + 8) * PSW + col] = make_float2(e2, e3);
        // no block sync: buffers are warp-private
    }

    // ---- row sums -> red; barrier also fences K-region reuse by V ----
    rsum0 += __shfl_xor_sync(0xffffffffu, rsum0, 1);
    rsum0 += __shfl_xor_sync(0xffffffffu, rsum0, 2);
    rsum1 += __shfl_xor_sync(0xffffffffu, rsum1, 1);
    rsum1 += __shfl_xor_sync(0xffffffffu, rsum1, 2);
    if (lx == 0) {
        red[ly * 16 + w]       = rsum0;
        red[(ly + 8) * 16 + w] = rsum1;
    }
    __syncthreads();   // all warps done with score phase + K buffers + Ps

    // ---- V tile 0 prologue (warp-private; K region now safe to reuse) ----
    const int s8 = w & 7;
    const int dhalf = (w >> 3) * 32;
    __nv_bfloat16* Vw = KVbf + w * VW_STRIDE;
    ld_vslice(Vh, Vl, 16 * s8, dhalf, Vw, lane);
    asm volatile("cp.async.commit_group;\n" ::: "memory");

    // ---- finish rowsum reduction -> inv[r] ----
    if (t < 256) {
        int r = t >> 4, x = t & 15;
        float s = red[r * 16 + x];
        s += __shfl_down_sync(0xffffffffu, s, 8, 16);
        s += __shfl_down_sync(0xffffffffu, s, 4, 16);
        s += __shfl_down_sync(0xffffffffu, s, 2, 16);
        s += __shfl_down_sync(0xffffffffu, s, 1, 16);
        if (x == 0) inv[r] = 1.0f / s;
    }
    __syncthreads();

    // ---- write normalized P (overlaps V tile-0 load latency) ----
    {
        int r = t >> 5, x = t & 31;
        float invr = inv[r];
        float* orow = attw + ((bh * SS_) + q0 + r) * (size_t)SS_;
        const int JMAX = num_kt * TKEY;
#pragma unroll 4
        for (int it = 0; it < 16; it++) {
            int col = it * 128 + x * 4;
            float4 v;
            if (col < JMAX) {
                float4 p = *(const float4*)&Ps[r * PSW + col];
                v = make_float4(p.x * invr, p.y * invr, p.z * invr, p.w * invr);
            } else {
                v = make_float4(0.f, 0.f, 0.f, 0.f);
            }
            *(float4*)&orow[col] = v;
        }
    }

    // =================== PV phase (no block syncs) ===================
    {
        float acc[4][4];
#pragma unroll
        for (int nf = 0; nf < 4; nf++)
#pragma unroll
            for (int i = 0; i < 4; i++) acc[nf][i] = 0.f;

        for (int kt2 = 0; kt2 < num_kt; kt2++) {
            if (kt2 + 1 < num_kt) {
                ld_vslice(Vh, Vl, (kt2 + 1) * TKEY + 16 * s8, dhalf,
                          Vw + ((kt2 + 1) & 1) * VW_STAGE, lane);
                asm volatile("cp.async.commit_group;\n" ::: "memory");
                asm volatile("cp.async.wait_group 1;\n" ::: "memory");
            } else {
                asm volatile("cp.async.wait_group 0;\n" ::: "memory");
            }
            __syncwarp();

            const __nv_bfloat16* Vbh = Vw + (kt2 & 1) * VW_STAGE;
            const __nv_bfloat16* Vbl = Vbh + 512;
            const int j0w = kt2 * TKEY + s8 * 16;

            // A-frag: P rows (ly, ly+8), keys j0w+2lx(+1), +8(+9)
            float2 p0 = *(const float2*)&Ps[ly * PSW + j0w + 2 * lx];
            float2 p1 = *(const float2*)&Ps[(ly + 8) * PSW + j0w + 2 * lx];
            float2 p2 = *(const float2*)&Ps[ly * PSW + j0w + 2 * lx + 8];
            float2 p3 = *(const float2*)&Ps[(ly + 8) * PSW + j0w + 2 * lx + 8];
            uint32_t pah[4], pal[4];
            split2(p0.x, p0.y, pah[0], pal[0]);
            split2(p1.x, p1.y, pah[1], pal[1]);
            split2(p2.x, p2.y, pah[2], pal[2]);
            split2(p3.x, p3.y, pah[3], pal[3]);

#pragma unroll
            for (int nf = 0; nf < 4; nf++) {
                const int drow = (nf * 8 + ly) * 16 + 2 * lx;
                uint32_t vh0 = *(const uint32_t*)&Vbh[drow];
                uint32_t vh1 = *(const uint32_t*)&Vbh[drow + 8];
                uint32_t vl0 = *(const uint32_t*)&Vbl[drow];
                uint32_t vl1 = *(const uint32_t*)&Vbl[drow + 8];
                MMA_BF16(acc[nf][0], acc[nf][1], acc[nf][2], acc[nf][3],
                         pah[0], pah[1], pah[2], pah[3], vh0, vh1);
                MMA_BF16(acc[nf][0], acc[nf][1], acc[nf][2], acc[nf][3],
                         pah[0], pah[1], pah[2], pah[3], vl0, vl1);
                MMA_BF16(acc[nf][0], acc[nf][1], acc[nf][2], acc[nf][3],
                         pal[0], pal[1], pal[2], pal[3], vh0, vh1);
            }
            // no block sync: V buffers are warp-private
        }
        __syncthreads();   // all warps done reading V region before rb reuse

        // ---- cross-warp reduce (8 partials per d-half) -> g_att ----
        float* rb = KVf;   // 16 warps x 16 rows x 34 = 8704 floats
#pragma unroll
        for (int nf = 0; nf < 4; nf++) {
            *(float2*)&rb[w * 544 + ly * 34 + nf * 8 + 2 * lx] =
                make_float2(acc[nf][0], acc[nf][1]);
            *(float2*)&rb[w * 544 + (ly + 8) * 34 + nf * 8 + 2 * lx] =
                make_float2(acc[nf][2], acc[nf][3]);
        }
        __syncthreads();
        {
            int r = t >> 5, c2 = (t & 31) * 2;
            int dh = c2 >> 5, loc = c2 & 31;
            float invr = inv[r];
            float2 s = make_float2(0.f, 0.f);
#pragma unroll
            for (int w2 = 0; w2 < 8; w2++) {
                float2 x2 = *(const float2*)&rb[(dh * 8 + w2) * 544 + r * 34 + loc];
                s.x += x2.x; s.y += x2.y;
            }
            s.x *= invr; s.y *= invr;
            *(float2*)&g_att[((size_t)(b * SS_) + q0 + r) * DD_ + h * 64 + c2] = s;
        }
    }
}

// ============================================================================
extern "C" void kernel_launch(void* const* d_in, const int* in_sizes, int n_in,
                              void* d_out, int out_size)
{
    (void)in_sizes; (void)n_in; (void)out_size;
    const float* x     = (const float*)d_in[0];
    const float* amask = (const float*)d_in[1];
    const float* W_in  = (const float*)d_in[2];
    const float* b_in  = (const float*)d_in[3];
    const float* W_out = (const float*)d_in[4];
    const float* b_out = (const float*)d_in[5];

    float* out  = (float*)d_out;
    float* attw = out + (size_t)BB_ * SS_ * DD_;   // tuple order: (out, attn_weights)

    cudaFuncSetAttribute(attn_kernel, cudaFuncAttributeMaxDynamicSharedMemorySize,
                         ATTN_SMEM_BYTES);
    cudaFuncSetAttribute(mma_gemm, cudaFuncAttributeMaxDynamicSharedMemorySize,
                         GSMEM_BYTES);

    // 0) transpose weights into K-major [N,K] scratch
    transpose_kernel<<<dim3(96, 32), dim3(32, 8)>>>(W_in, 3072, 0);
    transpose_kernel<<<dim3(32, 32), dim3(32, 8)>>>(W_out, 1024, 3072 * 1024);

    // 1) QKV projection -> bf16 hi/lo Q/K/V (V transposed)
    mma_gemm<<<dim3(24, 64), 256, GSMEM_BYTES>>>(x, 0, b_in, nullptr, 3072, 0);

    // 2) attention (warp-private staging, bf16-pair mma)
    attn_kernel<<<dim3(SS_ / 16, HH_, BB_), 512, ATTN_SMEM_BYTES>>>(amask, attw);

    // 3) output projection -> d_out head
    mma_gemm<<<dim3(8, 64), 256, GSMEM_BYTES>>>(nullptr, 3072 * 1024, b_out, out, 1024, 1);
}